// round 5
// baseline (speedup 1.0000x reference)
#include <cuda_runtime.h>

#define BATCH   2
#define SEQ     2048
#define DMODEL  1024
#define NHEADS  16
#define DK      64
#define MROWS   (BATCH*SEQ)      // 4096
#define QT      64               // q-tile / k-tile size in attention
#define PITCH   68               // smem pitch (floats), mult of 4, avoids bank repeats

// Scratch (allocation-free rule: __device__ globals)
__device__ float g_Qp[MROWS*DMODEL];
__device__ float g_Kp[MROWS*DMODEL];
__device__ float g_Vp[MROWS*DMODEL];
__device__ float g_ctx[MROWS*DMODEL];

// ---------------------------------------------------------------------------
// C[m][n] = sum_k A[m][k] * W[n][k] + bias[n]   (both operands K-contiguous)
// 128x128 tile, BK=8, 256 threads, 8x8 per thread.
// ---------------------------------------------------------------------------
__global__ __launch_bounds__(256) void gemm_nt_bias(
    const float* __restrict__ A, const float* __restrict__ W,
    const float* __restrict__ bias, float* __restrict__ C,
    int M, int N, int K)
{
    __shared__ float As[8][128];
    __shared__ float Ws[8][128];

    const int tid = threadIdx.x;
    const int bm = blockIdx.y * 128;
    const int bn = blockIdx.x * 128;
    const int tx = tid & 15;        // 0..15 -> n
    const int ty = tid >> 4;        // 0..15 -> m
    const int lr = tid >> 1;        // load row 0..127
    const int lc = (tid & 1) * 4;   // load col 0 or 4

    const float* Ag = A + (size_t)(bm + lr) * K + lc;
    const float* Wg = W + (size_t)(bn + lr) * K + lc;

    float acc[8][8];
#pragma unroll
    for (int i = 0; i < 8; i++)
#pragma unroll
        for (int j = 0; j < 8; j++) acc[i][j] = 0.f;

    for (int k0 = 0; k0 < K; k0 += 8) {
        float4 a4 = *(const float4*)(Ag + k0);
        float4 w4 = *(const float4*)(Wg + k0);
        As[lc + 0][lr] = a4.x; As[lc + 1][lr] = a4.y;
        As[lc + 2][lr] = a4.z; As[lc + 3][lr] = a4.w;
        Ws[lc + 0][lr] = w4.x; Ws[lc + 1][lr] = w4.y;
        Ws[lc + 2][lr] = w4.z; Ws[lc + 3][lr] = w4.w;
        __syncthreads();

#pragma unroll
        for (int kk = 0; kk < 8; kk++) {
            float4 a0 = *(const float4*)&As[kk][ty * 8];
            float4 a1 = *(const float4*)&As[kk][ty * 8 + 4];
            float4 w0 = *(const float4*)&Ws[kk][tx * 8];
            float4 w1 = *(const float4*)&Ws[kk][tx * 8 + 4];
            float ra[8] = {a0.x, a0.y, a0.z, a0.w, a1.x, a1.y, a1.z, a1.w};
            float rw[8] = {w0.x, w0.y, w0.z, w0.w, w1.x, w1.y, w1.z, w1.w};
#pragma unroll
            for (int i = 0; i < 8; i++)
#pragma unroll
                for (int j = 0; j < 8; j++)
                    acc[i][j] = fmaf(ra[i], rw[j], acc[i][j]);
        }
        __syncthreads();
    }

#pragma unroll
    for (int i = 0; i < 8; i++) {
        size_t row = (size_t)(bm + ty * 8 + i);
#pragma unroll
        for (int j = 0; j < 8; j += 4) {
            int col = bn + tx * 8 + j;
            float4 o;
            o.x = acc[i][j + 0] + bias[col + 0];
            o.y = acc[i][j + 1] + bias[col + 1];
            o.z = acc[i][j + 2] + bias[col + 2];
            o.w = acc[i][j + 3] + bias[col + 3];
            *(float4*)&C[row * N + col] = o;
        }
    }
}

// ---------------------------------------------------------------------------
// Fused attention: per CTA one (b, h, 64-row q-tile).
// Phase 1: stream k-tiles, compute scaled scores, write raw into attn gmem,
//          track online row max m / sum l.
// Phase 2: re-read raw scores, normalize in place, accumulate O = P @ V.
// Each CTA owns its q-rows fully -> no cross-CTA dependency.
// ---------------------------------------------------------------------------
__global__ __launch_bounds__(256) void attn_kernel(
    const float* __restrict__ Qp, const float* __restrict__ Kp,
    const float* __restrict__ Vp, float* __restrict__ attn,
    float* __restrict__ ctx)
{
    __shared__ float sA[QT * PITCH]; // Q^T (phase1) / V (phase2)
    __shared__ float sB[QT * PITCH]; // K^T (phase1) / P^T (phase2)

    const int b  = blockIdx.z;
    const int h  = blockIdx.y;
    const int q0 = blockIdx.x * QT;
    const int tid = threadIdx.x;
    const int tx = tid & 15, ty = tid >> 4;
    const int tx4 = tx * 4, ty4 = ty * 4;

    const float* Qbase = Qp + (size_t)b * SEQ * DMODEL + h * DK;
    const float* Kbase = Kp + (size_t)b * SEQ * DMODEL + h * DK;
    const float* Vbase = Vp + (size_t)b * SEQ * DMODEL + h * DK;
    float* attnBase = attn + ((size_t)(b * NHEADS + h)) * SEQ * SEQ;

    // Load Q tile transposed: sA[c][r]
    for (int i = tid; i < QT * 16; i += 256) {
        int r = i >> 4;
        int c4 = (i & 15) * 4;
        float4 v = *(const float4*)&Qbase[(size_t)(q0 + r) * DMODEL + c4];
        sA[(c4 + 0) * PITCH + r] = v.x;
        sA[(c4 + 1) * PITCH + r] = v.y;
        sA[(c4 + 2) * PITCH + r] = v.z;
        sA[(c4 + 3) * PITCH + r] = v.w;
    }

    float m[4], l[4];
#pragma unroll
    for (int i = 0; i < 4; i++) { m[i] = -1e30f; l[i] = 0.f; }
    __syncthreads();

    const float scale = 0.125f; // 1/sqrt(64)

    // ---------------- Phase 1 ----------------
    for (int kt = 0; kt < SEQ / QT; kt++) {
        for (int i = tid; i < QT * 16; i += 256) {
            int r = i >> 4;
            int c4 = (i & 15) * 4;
            float4 v = *(const float4*)&Kbase[(size_t)(kt * QT + r) * DMODEL + c4];
            sB[(c4 + 0) * PITCH + r] = v.x;
            sB[(c4 + 1) * PITCH + r] = v.y;
            sB[(c4 + 2) * PITCH + r] = v.z;
            sB[(c4 + 3) * PITCH + r] = v.w;
        }
        __syncthreads();

        float s[4][4];
#pragma unroll
        for (int i = 0; i < 4; i++)
#pragma unroll
            for (int j = 0; j < 4; j++) s[i][j] = 0.f;

#pragma unroll 4
        for (int kk = 0; kk < DK; kk++) {
            float4 qv = *(const float4*)&sA[kk * PITCH + ty4];
            float4 kv = *(const float4*)&sB[kk * PITCH + tx4];
            float rq[4] = {qv.x, qv.y, qv.z, qv.w};
            float rk[4] = {kv.x, kv.y, kv.z, kv.w};
#pragma unroll
            for (int i = 0; i < 4; i++)
#pragma unroll
                for (int j = 0; j < 4; j++)
                    s[i][j] = fmaf(rq[i], rk[j], s[i][j]);
        }

#pragma unroll
        for (int i = 0; i < 4; i++) {
#pragma unroll
            for (int j = 0; j < 4; j++) s[i][j] *= scale;
            // write raw scaled scores (scratch in the attn output region)
            float4 st = {s[i][0], s[i][1], s[i][2], s[i][3]};
            *(float4*)&attnBase[(size_t)(q0 + ty4 + i) * SEQ + kt * QT + tx4] = st;
            // online stats across the 16 tx lanes (half-warp butterflies)
            float tm = fmaxf(fmaxf(s[i][0], s[i][1]), fmaxf(s[i][2], s[i][3]));
#pragma unroll
            for (int off = 8; off >= 1; off >>= 1)
                tm = fmaxf(tm, __shfl_xor_sync(0xffffffffu, tm, off));
            float nm = fmaxf(m[i], tm);
            float rs = __expf(s[i][0] - nm) + __expf(s[i][1] - nm) +
                       __expf(s[i][2] - nm) + __expf(s[i][3] - nm);
#pragma unroll
            for (int off = 8; off >= 1; off >>= 1)
                rs += __shfl_xor_sync(0xffffffffu, rs, off);
            l[i] = l[i] * __expf(m[i] - nm) + rs;
            m[i] = nm;
        }
        __syncthreads();
    }

    float inv_l[4];
#pragma unroll
    for (int i = 0; i < 4; i++) inv_l[i] = 1.f / l[i];

    float o[4][4];
#pragma unroll
    for (int i = 0; i < 4; i++)
#pragma unroll
        for (int j = 0; j < 4; j++) o[i][j] = 0.f;

    // ---------------- Phase 2 ----------------
    for (int kt = 0; kt < SEQ / QT; kt++) {
        // V tile direct layout: sA[r][c]
        for (int i = tid; i < QT * 16; i += 256) {
            int r = i >> 4;
            int c4 = (i & 15) * 4;
            float4 v = *(const float4*)&Vbase[(size_t)(kt * QT + r) * DMODEL + c4];
            *(float4*)&sA[r * PITCH + c4] = v;
        }
        // re-read own raw scores, normalize, write back + P^T into sB
#pragma unroll
        for (int i = 0; i < 4; i++) {
            float4 sv = *(const float4*)&attnBase[(size_t)(q0 + ty4 + i) * SEQ + kt * QT + tx4];
            float p0 = __expf(sv.x - m[i]) * inv_l[i];
            float p1 = __expf(sv.y - m[i]) * inv_l[i];
            float p2 = __expf(sv.z - m[i]) * inv_l[i];
            float p3 = __expf(sv.w - m[i]) * inv_l[i];
            float4 pv = {p0, p1, p2, p3};
            *(float4*)&attnBase[(size_t)(q0 + ty4 + i) * SEQ + kt * QT + tx4] = pv;
            sB[(tx4 + 0) * PITCH + ty4 + i] = p0;
            sB[(tx4 + 1) * PITCH + ty4 + i] = p1;
            sB[(tx4 + 2) * PITCH + ty4 + i] = p2;
            sB[(tx4 + 3) * PITCH + ty4 + i] = p3;
        }
        __syncthreads();

#pragma unroll 4
        for (int kk = 0; kk < QT; kk++) {
            float4 pv = *(const float4*)&sB[kk * PITCH + ty4];
            float4 vv = *(const float4*)&sA[kk * PITCH + tx4];
            float rp[4] = {pv.x, pv.y, pv.z, pv.w};
            float rv[4] = {vv.x, vv.y, vv.z, vv.w};
#pragma unroll
            for (int i = 0; i < 4; i++)
#pragma unroll
                for (int j = 0; j < 4; j++)
                    o[i][j] = fmaf(rp[i], rv[j], o[i][j]);
        }
        __syncthreads();
    }

    float* ctxBase = ctx + (size_t)b * SEQ * DMODEL + h * DK;
#pragma unroll
    for (int i = 0; i < 4; i++) {
        float4 ov = {o[i][0], o[i][1], o[i][2], o[i][3]};
        *(float4*)&ctxBase[(size_t)(q0 + ty4 + i) * DMODEL + tx4] = ov;
    }
}

// ---------------------------------------------------------------------------
extern "C" void kernel_launch(void* const* d_in, const int* in_sizes, int n_in,
                              void* d_out, int out_size)
{
    const float* q  = (const float*)d_in[0];
    const float* k  = (const float*)d_in[1];
    const float* v  = (const float*)d_in[2];
    const float* wq = (const float*)d_in[3];
    const float* bq = (const float*)d_in[4];
    const float* wk = (const float*)d_in[5];
    const float* bk = (const float*)d_in[6];
    const float* wv = (const float*)d_in[7];
    const float* bv = (const float*)d_in[8];
    const float* wo = (const float*)d_in[9];
    const float* bo = (const float*)d_in[10];

    float* out  = (float*)d_out;
    float* attn = out + (size_t)MROWS * DMODEL;   // [B,H,S,S] after [B,S,D]

    float *Qp, *Kp, *Vp, *ctx;
    cudaGetSymbolAddress((void**)&Qp,  g_Qp);
    cudaGetSymbolAddress((void**)&Kp,  g_Kp);
    cudaGetSymbolAddress((void**)&Vp,  g_Vp);
    cudaGetSymbolAddress((void**)&ctx, g_ctx);

    dim3 ggrid(DMODEL / 128, MROWS / 128); // (8, 32)
    gemm_nt_bias<<<ggrid, 256>>>(q, wq, bq, Qp, MROWS, DMODEL, DMODEL);
    gemm_nt_bias<<<ggrid, 256>>>(k, wk, bk, Kp, MROWS, DMODEL, DMODEL);
    gemm_nt_bias<<<ggrid, 256>>>(v, wv, bv, Vp, MROWS, DMODEL, DMODEL);

    attn_kernel<<<dim3(SEQ / QT, NHEADS, BATCH), 256>>>(Qp, Kp, Vp, attn, ctx);

    gemm_nt_bias<<<ggrid, 256>>>(ctx, wo, bo, out, MROWS, DMODEL, DMODEL);
}

// round 7
// speedup vs baseline: 1.0697x; 1.0697x over previous
#include <cuda_runtime.h>
#include <cuda_bf16.h>
#include <stdint.h>

#define BATCH   2
#define SEQ     2048
#define DMODEL  1024
#define NHEADS  16
#define DK      64
#define MROWS   (BATCH*SEQ)      // 4096

// Scratch (__device__ globals: allocation-free rule)
__device__ float g_Qp[MROWS*DMODEL];
__device__ float g_Kp[MROWS*DMODEL];
__device__ float g_Vp[MROWS*DMODEL];
__device__ float g_ctx[MROWS*DMODEL];
__device__ __nv_bfloat16 g_Ahi[MROWS*DMODEL];
__device__ __nv_bfloat16 g_Alo[MROWS*DMODEL];
__device__ __nv_bfloat16 g_Whi[DMODEL*DMODEL];
__device__ __nv_bfloat16 g_Wlo[DMODEL*DMODEL];

__device__ __forceinline__ uint32_t smem_u32(const void* p) {
    uint32_t a;
    asm("{ .reg .u64 t; cvta.to.shared.u64 t, %1; cvt.u32.u64 %0, t; }" : "=r"(a) : "l"(p));
    return a;
}

#define LDSM4(r, addr) asm volatile( \
    "ldmatrix.sync.aligned.m8n8.x4.shared.b16 {%0,%1,%2,%3}, [%4];" \
    : "=r"((r)[0]), "=r"((r)[1]), "=r"((r)[2]), "=r"((r)[3]) : "r"(addr))

#define MMA_BF16(d, a, b) asm volatile( \
    "mma.sync.aligned.m16n8k16.row.col.f32.bf16.bf16.f32 " \
    "{%0,%1,%2,%3}, {%4,%5,%6,%7}, {%8,%9}, {%0,%1,%2,%3};" \
    : "+f"((d)[0]), "+f"((d)[1]), "+f"((d)[2]), "+f"((d)[3]) \
    : "r"((a)[0]), "r"((a)[1]), "r"((a)[2]), "r"((a)[3]), "r"((b)[0]), "r"((b)[1]))

// ---------------------------------------------------------------------------
// fp32 -> (hi, lo) bf16 split
// ---------------------------------------------------------------------------
__global__ __launch_bounds__(256) void cvt_kernel(
    const float* __restrict__ x, __nv_bfloat16* __restrict__ hi,
    __nv_bfloat16* __restrict__ lo, int n)
{
    int i = (blockIdx.x * 256 + threadIdx.x) * 4;
    if (i >= n) return;
    float4 v = *(const float4*)(x + i);
    __nv_bfloat16 h0 = __float2bfloat16(v.x), h1 = __float2bfloat16(v.y);
    __nv_bfloat16 h2 = __float2bfloat16(v.z), h3 = __float2bfloat16(v.w);
    *(__nv_bfloat162*)(hi + i)     = __halves2bfloat162(h0, h1);
    *(__nv_bfloat162*)(hi + i + 2) = __halves2bfloat162(h2, h3);
    *(__nv_bfloat162*)(lo + i)     = __floats2bfloat162_rn(
        v.x - __bfloat162float(h0), v.y - __bfloat162float(h1));
    *(__nv_bfloat162*)(lo + i + 2) = __floats2bfloat162_rn(
        v.z - __bfloat162float(h2), v.w - __bfloat162float(h3));
}

// ---------------------------------------------------------------------------
// mma.sync GEMM: C[M,N] = A[M,K] @ W[N,K]^T + bias, split-bf16 (3 passes).
// 128x128 tile, K-chunk 64 bf16, 256 threads = 8 warps (2m x 4n),
// warp tile m64 x n32 = 4x4 mma tiles. smem rows: 64 bf16 = 128B, SW128 swz.
// ---------------------------------------------------------------------------
#define GEMM_SMEM 65536

__device__ __forceinline__ uint32_t tile_addr(uint32_t base, int row, int kb) {
    return base + row * 128 + ((((kb >> 4) ^ (row & 7))) << 4) + (kb & 15);
}

__global__ __launch_bounds__(256) void gemm_mma(
    const __nv_bfloat16* __restrict__ Ahi, const __nv_bfloat16* __restrict__ Alo,
    const __nv_bfloat16* __restrict__ Whi, const __nv_bfloat16* __restrict__ Wlo,
    const float* __restrict__ bias, float* __restrict__ C,
    int M, int N, int K)
{
    extern __shared__ char sm[];
    const uint32_t sb = smem_u32(sm);
    const uint32_t sAhi = sb, sAlo = sb + 16384, sBhi = sb + 32768, sBlo = sb + 49152;

    const int tid = threadIdx.x, lane = tid & 31, wid = tid >> 5;
    const int wm = (wid >> 2) * 64, wn = (wid & 3) * 32;
    const int bm = blockIdx.y * 128, bn = blockIdx.x * 128;

    // ldmatrix lane address components
    const int aRow = lane & 15,                         aKb = (lane >> 4) * 16;
    const int bRow = (lane & 7) + ((lane >> 4) << 3),   bKb = ((lane >> 3) & 1) * 16;

    float acc[4][4][4];
#pragma unroll
    for (int i = 0; i < 4; i++)
#pragma unroll
        for (int j = 0; j < 4; j++)
#pragma unroll
            for (int r = 0; r < 4; r++) acc[i][j][r] = 0.f;

    for (int ch = 0; ch < K / 64; ch++) {
        const int k0 = ch * 64;
#pragma unroll
        for (int s = 0; s < 4; s++) {
            int idx = tid + s * 256;            // 0..1023
            int r = idx >> 3, g = idx & 7;      // row 0..127, 16B group 0..7
            int so = r * 128 + ((g ^ (r & 7)) << 4);
            const size_t ga = (size_t)(bm + r) * K + k0 + g * 8;
            const size_t gb = (size_t)(bn + r) * K + k0 + g * 8;
            *(uint4*)(sm + so)         = *(const uint4*)(Ahi + ga);
            *(uint4*)(sm + 16384 + so) = *(const uint4*)(Alo + ga);
            *(uint4*)(sm + 32768 + so) = *(const uint4*)(Whi + gb);
            *(uint4*)(sm + 49152 + so) = *(const uint4*)(Wlo + gb);
        }
        __syncthreads();

#pragma unroll
        for (int ks = 0; ks < 4; ks++) {
            const int kb = ks * 32;
            uint32_t ah[4][4], bh[2][4];
#pragma unroll
            for (int mt = 0; mt < 4; mt++)
                LDSM4(ah[mt], tile_addr(sAhi, wm + mt * 16 + aRow, kb + aKb));
#pragma unroll
            for (int nt2 = 0; nt2 < 2; nt2++)
                LDSM4(bh[nt2], tile_addr(sBhi, wn + nt2 * 16 + bRow, kb + bKb));
#pragma unroll
            for (int mt = 0; mt < 4; mt++)
#pragma unroll
                for (int nt = 0; nt < 4; nt++)
                    MMA_BF16(acc[mt][nt], ah[mt], &bh[nt >> 1][(nt & 1) * 2]);

            uint32_t al[4][4];
#pragma unroll
            for (int mt = 0; mt < 4; mt++)
                LDSM4(al[mt], tile_addr(sAlo, wm + mt * 16 + aRow, kb + aKb));
#pragma unroll
            for (int mt = 0; mt < 4; mt++)
#pragma unroll
                for (int nt = 0; nt < 4; nt++)
                    MMA_BF16(acc[mt][nt], al[mt], &bh[nt >> 1][(nt & 1) * 2]);

            uint32_t bl[2][4];
#pragma unroll
            for (int nt2 = 0; nt2 < 2; nt2++)
                LDSM4(bl[nt2], tile_addr(sBlo, wn + nt2 * 16 + bRow, kb + bKb));
#pragma unroll
            for (int mt = 0; mt < 4; mt++)
#pragma unroll
                for (int nt = 0; nt < 4; nt++)
                    MMA_BF16(acc[mt][nt], ah[mt], &bl[nt >> 1][(nt & 1) * 2]);
        }
        __syncthreads();
    }

    const int r0 = lane >> 2, c0 = (lane & 3) * 2;
#pragma unroll
    for (int mt = 0; mt < 4; mt++) {
        int m = bm + wm + mt * 16 + r0;
#pragma unroll
        for (int nt = 0; nt < 4; nt++) {
            int n = bn + wn + nt * 8 + c0;
            float2 v0 = {acc[mt][nt][0] + bias[n], acc[mt][nt][1] + bias[n + 1]};
            float2 v1 = {acc[mt][nt][2] + bias[n], acc[mt][nt][3] + bias[n + 1]};
            *(float2*)&C[(size_t)m * N + n] = v0;
            *(float2*)&C[(size_t)(m + 8) * N + n] = v1;
        }
    }
}

// ---------------------------------------------------------------------------
// Fused attention, 128x128 tiles, 8x8 register blocking, fp32.
// Phase 1: scores -> raw scratch in attn gmem + online row max/sum.
// Phase 2: normalize in place + O = P @ V (64-kv chunks).
// Swizzled transposed tiles: idx(kk,q) = kk*128 + (q ^ (((kk>>2)&15)<<2)).
// ---------------------------------------------------------------------------
#define ATTN_SMEM 66560

__device__ __forceinline__ int sqz(int kk, int q) {
    return kk * 128 + (q ^ (((kk >> 2) & 15) << 2));
}

__global__ __launch_bounds__(256) void attn_kernel(
    const float* __restrict__ Qp, const float* __restrict__ Kp,
    const float* __restrict__ Vp, float* __restrict__ attn,
    float* __restrict__ ctx)
{
    extern __shared__ float sf[];
    float* sQ  = sf;           // phase1: Q^T [64][128] swz
    float* sK  = sf + 8192;    // phase1: K^T [64][128] swz
    float* sPT = sf;           // phase2: P^T [64][128] swz
    float* sV  = sf + 8192;    // phase2: V [64][68]
    float* sM  = sf + 16384;   // [128]
    float* sL  = sf + 16512;   // [128] (inverse sums)

    const int b  = blockIdx.z;
    const int h  = blockIdx.y;
    const int q0 = blockIdx.x * 128;
    const int tid = threadIdx.x;
    const int tx = tid & 15, ty = tid >> 4;
    const int tx8 = tx * 8, ty8 = ty * 8;

    const float* Qbase = Qp + (size_t)b * SEQ * DMODEL + h * DK;
    const float* Kbase = Kp + (size_t)b * SEQ * DMODEL + h * DK;
    const float* Vbase = Vp + (size_t)b * SEQ * DMODEL + h * DK;
    float* attnBase = attn + ((size_t)(b * NHEADS + h)) * SEQ * SEQ;

    // Load Q^T (transposed, swizzled)
#pragma unroll
    for (int s = 0; s < 8; s++) {
        int i = tid + s * 256;             // 0..2047
        int r = i >> 4, c4 = (i & 15) * 4; // q row, dk group
        float4 v = *(const float4*)&Qbase[(size_t)(q0 + r) * DMODEL + c4];
        sQ[sqz(c4 + 0, r)] = v.x;
        sQ[sqz(c4 + 1, r)] = v.y;
        sQ[sqz(c4 + 2, r)] = v.z;
        sQ[sqz(c4 + 3, r)] = v.w;
    }

    float m[8], l[8];
#pragma unroll
    for (int i = 0; i < 8; i++) { m[i] = -1e30f; l[i] = 0.f; }
    __syncthreads();

    const float scale = 0.125f; // 1/sqrt(64)

    // ---------------- Phase 1 ----------------
    for (int kt = 0; kt < SEQ / 128; kt++) {
#pragma unroll
        for (int s = 0; s < 8; s++) {
            int i = tid + s * 256;
            int r = i >> 4, c4 = (i & 15) * 4;
            float4 v = *(const float4*)&Kbase[(size_t)(kt * 128 + r) * DMODEL + c4];
            sK[sqz(c4 + 0, r)] = v.x;
            sK[sqz(c4 + 1, r)] = v.y;
            sK[sqz(c4 + 2, r)] = v.z;
            sK[sqz(c4 + 3, r)] = v.w;
        }
        __syncthreads();

        float s8[8][8];
#pragma unroll
        for (int i = 0; i < 8; i++)
#pragma unroll
            for (int j = 0; j < 8; j++) s8[i][j] = 0.f;

#pragma unroll 4
        for (int kk = 0; kk < DK; kk++) {
            float4 qa = *(const float4*)&sQ[sqz(kk, ty8)];
            float4 qb = *(const float4*)&sQ[sqz(kk, ty8 + 4)];
            float4 ka = *(const float4*)&sK[sqz(kk, tx8)];
            float4 kb = *(const float4*)&sK[sqz(kk, tx8 + 4)];
            float rq[8] = {qa.x, qa.y, qa.z, qa.w, qb.x, qb.y, qb.z, qb.w};
            float rk[8] = {ka.x, ka.y, ka.z, ka.w, kb.x, kb.y, kb.z, kb.w};
#pragma unroll
            for (int i = 0; i < 8; i++)
#pragma unroll
                for (int j = 0; j < 8; j++)
                    s8[i][j] = fmaf(rq[i], rk[j], s8[i][j]);
        }

#pragma unroll
        for (int i = 0; i < 8; i++) {
#pragma unroll
            for (int j = 0; j < 8; j++) s8[i][j] *= scale;
            float4 st0 = {s8[i][0], s8[i][1], s8[i][2], s8[i][3]};
            float4 st1 = {s8[i][4], s8[i][5], s8[i][6], s8[i][7]};
            float* dst = &attnBase[(size_t)(q0 + ty8 + i) * SEQ + kt * 128 + tx8];
            *(float4*)dst = st0;
            *(float4*)(dst + 4) = st1;
            float tm = s8[i][0];
#pragma unroll
            for (int j = 1; j < 8; j++) tm = fmaxf(tm, s8[i][j]);
#pragma unroll
            for (int off = 8; off >= 1; off >>= 1)
                tm = fmaxf(tm, __shfl_xor_sync(0xffffffffu, tm, off));
            float nm = fmaxf(m[i], tm);
            float rs = 0.f;
#pragma unroll
            for (int j = 0; j < 8; j++) rs += __expf(s8[i][j] - nm);
#pragma unroll
            for (int off = 8; off >= 1; off >>= 1)
                rs += __shfl_xor_sync(0xffffffffu, rs, off);
            l[i] = l[i] * __expf(m[i] - nm) + rs;
            m[i] = nm;
        }
        __syncthreads();
    }

    // Publish per-row stats to smem for phase 2
    if (tx == 0) {
#pragma unroll
        for (int i = 0; i < 8; i++) {
            sM[ty8 + i] = m[i];
            sL[ty8 + i] = 1.f / l[i];
        }
    }
    __syncthreads();

    // ---------------- Phase 2 ----------------
    const int tx2 = tid & 7, ty2 = tid >> 3;     // 8 x 32
    const int dk8 = tx2 * 8, qr4 = ty2 * 4;      // thread tile 4q x 8dk

    float o[4][8];
#pragma unroll
    for (int i = 0; i < 4; i++)
#pragma unroll
        for (int j = 0; j < 8; j++) o[i][j] = 0.f;

    for (int ck = 0; ck < SEQ / 64; ck++) {
        // V chunk [64 kv][64 dk], pitch 68
#pragma unroll
        for (int s = 0; s < 4; s++) {
            int i = tid + s * 256;             // 0..1023
            int r = i >> 4, c4 = (i & 15) * 4;
            float4 v = *(const float4*)&Vbase[(size_t)(ck * 64 + r) * DMODEL + c4];
            *(float4*)&sV[r * 68 + c4] = v;
        }
        // P chunk: read raw scores, normalize, write back + P^T into smem
#pragma unroll
        for (int s = 0; s < 8; s++) {
            int i = tid + s * 256;             // 0..2047
            int qq = i >> 4, k4 = (i & 15) * 4;
            float* gp = &attnBase[(size_t)(q0 + qq) * SEQ + ck * 64 + k4];
            float4 sv = *(const float4*)gp;
            float mq = sM[qq], il = sL[qq];
            float p0 = __expf(sv.x - mq) * il;
            float p1 = __expf(sv.y - mq) * il;
            float p2 = __expf(sv.z - mq) * il;
            float p3 = __expf(sv.w - mq) * il;
            float4 pv = {p0, p1, p2, p3};
            *(float4*)gp = pv;
            sPT[sqz(k4 + 0, qq)] = p0;
            sPT[sqz(k4 + 1, qq)] = p1;
            sPT[sqz(k4 + 2, qq)] = p2;
            sPT[sqz(k4 + 3, qq)] = p3;
        }
        __syncthreads();

#pragma unroll 4
        for (int kk = 0; kk < 64; kk++) {
            float4 pa = *(const float4*)&sPT[sqz(kk, qr4)];
            float4 va = *(const float4*)&sV[kk * 68 + dk8];
            float4 vb = *(const float4*)&sV[kk * 68 + dk8 + 4];
            float rp[4] = {pa.x, pa.y, pa.z, pa.w};
            float rv[8] = {va.x, va.y, va.z, va.w, vb.x, vb.y, vb.z, vb.w};
#pragma unroll
            for (int i = 0; i < 4; i++)
#pragma unroll
                for (int j = 0; j < 8; j++)
                    o[i][j] = fmaf(rp[i], rv[j], o[i][j]);
        }
        __syncthreads();
    }

    float* ctxBase = ctx + (size_t)b * SEQ * DMODEL + h * DK;
#pragma unroll
    for (int i = 0; i < 4; i++) {
        float4 o0 = {o[i][0], o[i][1], o[i][2], o[i][3]};
        float4 o1 = {o[i][4], o[i][5], o[i][6], o[i][7]};
        float* dst = &ctxBase[(size_t)(q0 + qr4 + i) * DMODEL + dk8];
        *(float4*)dst = o0;
        *(float4*)(dst + 4) = o1;
    }
}

// ---------------------------------------------------------------------------
extern "C" void kernel_launch(void* const* d_in, const int* in_sizes, int n_in,
                              void* d_out, int out_size)
{
    const float* q  = (const float*)d_in[0];
    const float* k  = (const float*)d_in[1];
    const float* v  = (const float*)d_in[2];
    const float* wq = (const float*)d_in[3];
    const float* bq = (const float*)d_in[4];
    const float* wk = (const float*)d_in[5];
    const float* bk = (const float*)d_in[6];
    const float* wv = (const float*)d_in[7];
    const float* bv = (const float*)d_in[8];
    const float* wo = (const float*)d_in[9];
    const float* bo = (const float*)d_in[10];

    float* out  = (float*)d_out;
    float* attn = out + (size_t)MROWS * DMODEL;

    float *Qp, *Kp, *Vp, *ctx;
    __nv_bfloat16 *Ahi, *Alo, *Whi, *Wlo;
    cudaGetSymbolAddress((void**)&Qp,  g_Qp);
    cudaGetSymbolAddress((void**)&Kp,  g_Kp);
    cudaGetSymbolAddress((void**)&Vp,  g_Vp);
    cudaGetSymbolAddress((void**)&ctx, g_ctx);
    cudaGetSymbolAddress((void**)&Ahi, g_Ahi);
    cudaGetSymbolAddress((void**)&Alo, g_Alo);
    cudaGetSymbolAddress((void**)&Whi, g_Whi);
    cudaGetSymbolAddress((void**)&Wlo, g_Wlo);

    static int attr_set = 0;
    if (!attr_set) {
        cudaFuncSetAttribute(gemm_mma, cudaFuncAttributeMaxDynamicSharedMemorySize, GEMM_SMEM);
        cudaFuncSetAttribute(attn_kernel, cudaFuncAttributeMaxDynamicSharedMemorySize, ATTN_SMEM);
        attr_set = 1;
    }

    const int nA = MROWS * DMODEL;     // 4M
    const int nW = DMODEL * DMODEL;    // 1M
    dim3 cgA(nA / 4 / 256), cgW(nW / 4 / 256);
    dim3 ggrid(DMODEL / 128, MROWS / 128); // (8, 32)

    cvt_kernel<<<cgA, 256>>>(q, Ahi, Alo, nA);
    cvt_kernel<<<cgW, 256>>>(wq, Whi, Wlo, nW);
    gemm_mma<<<ggrid, 256, GEMM_SMEM>>>(Ahi, Alo, Whi, Wlo, bq, Qp, MROWS, DMODEL, DMODEL);

    cvt_kernel<<<cgA, 256>>>(k, Ahi, Alo, nA);
    cvt_kernel<<<cgW, 256>>>(wk, Whi, Wlo, nW);
    gemm_mma<<<ggrid, 256, GEMM_SMEM>>>(Ahi, Alo, Whi, Wlo, bk, Kp, MROWS, DMODEL, DMODEL);

    cvt_kernel<<<cgA, 256>>>(v, Ahi, Alo, nA);
    cvt_kernel<<<cgW, 256>>>(wv, Whi, Wlo, nW);
    gemm_mma<<<ggrid, 256, GEMM_SMEM>>>(Ahi, Alo, Whi, Wlo, bv, Vp, MROWS, DMODEL, DMODEL);

    attn_kernel<<<dim3(SEQ / 128, NHEADS, BATCH), 256, ATTN_SMEM>>>(Qp, Kp, Vp, attn, ctx);

    cvt_kernel<<<cgA, 256>>>(ctx, Ahi, Alo, nA);
    cvt_kernel<<<cgW, 256>>>(wo, Whi, Wlo, nW);
    gemm_mma<<<ggrid, 256, GEMM_SMEM>>>(Ahi, Alo, Whi, Wlo, bo, out, MROWS, DMODEL, DMODEL);
}

// round 8
// speedup vs baseline: 1.2850x; 1.2012x over previous
#include <cuda_runtime.h>
#include <cuda_bf16.h>
#include <stdint.h>

#define BATCH   2
#define SEQ     2048
#define DMODEL  1024
#define NHEADS  16
#define DK      64
#define MROWS   (BATCH*SEQ)      // 4096

// Scratch (__device__ globals: allocation-free rule)
__device__ float g_Qp[MROWS*DMODEL];
__device__ float g_Kp[MROWS*DMODEL];
__device__ float g_Vp[MROWS*DMODEL];
__device__ float g_ctx[MROWS*DMODEL];
// per-tensor bf16 split buffers (lets us front-load all cvts -> ncu -s 5 lands on gemm_mma)
__device__ __nv_bfloat16 g_A1hi[MROWS*DMODEL], g_A1lo[MROWS*DMODEL];
__device__ __nv_bfloat16 g_A2hi[MROWS*DMODEL], g_A2lo[MROWS*DMODEL];
__device__ __nv_bfloat16 g_A3hi[MROWS*DMODEL], g_A3lo[MROWS*DMODEL];
__device__ __nv_bfloat16 g_W1hi[DMODEL*DMODEL], g_W1lo[DMODEL*DMODEL];
__device__ __nv_bfloat16 g_W2hi[DMODEL*DMODEL], g_W2lo[DMODEL*DMODEL];

__device__ __forceinline__ uint32_t smem_u32(const void* p) {
    uint32_t a;
    asm("{ .reg .u64 t; cvta.to.shared.u64 t, %1; cvt.u32.u64 %0, t; }" : "=r"(a) : "l"(p));
    return a;
}

#define LDSM4(r, addr) asm volatile( \
    "ldmatrix.sync.aligned.m8n8.x4.shared.b16 {%0,%1,%2,%3}, [%4];" \
    : "=r"((r)[0]), "=r"((r)[1]), "=r"((r)[2]), "=r"((r)[3]) : "r"(addr))

#define MMA_BF16(d, a, b) asm volatile( \
    "mma.sync.aligned.m16n8k16.row.col.f32.bf16.bf16.f32 " \
    "{%0,%1,%2,%3}, {%4,%5,%6,%7}, {%8,%9}, {%0,%1,%2,%3};" \
    : "+f"((d)[0]), "+f"((d)[1]), "+f"((d)[2]), "+f"((d)[3]) \
    : "r"((a)[0]), "r"((a)[1]), "r"((a)[2]), "r"((a)[3]), "r"((b)[0]), "r"((b)[1]))

// ---------------------------------------------------------------------------
// fp32 -> (hi, lo) bf16 split
// ---------------------------------------------------------------------------
__global__ __launch_bounds__(256) void cvt_kernel(
    const float* __restrict__ x, __nv_bfloat16* __restrict__ hi,
    __nv_bfloat16* __restrict__ lo, int n)
{
    int i = (blockIdx.x * 256 + threadIdx.x) * 4;
    if (i >= n) return;
    float4 v = *(const float4*)(x + i);
    __nv_bfloat16 h0 = __float2bfloat16(v.x), h1 = __float2bfloat16(v.y);
    __nv_bfloat16 h2 = __float2bfloat16(v.z), h3 = __float2bfloat16(v.w);
    *(__nv_bfloat162*)(hi + i)     = __halves2bfloat162(h0, h1);
    *(__nv_bfloat162*)(hi + i + 2) = __halves2bfloat162(h2, h3);
    *(__nv_bfloat162*)(lo + i)     = __floats2bfloat162_rn(
        v.x - __bfloat162float(h0), v.y - __bfloat162float(h1));
    *(__nv_bfloat162*)(lo + i + 2) = __floats2bfloat162_rn(
        v.z - __bfloat162float(h2), v.w - __bfloat162float(h3));
}

// ---------------------------------------------------------------------------
// mma.sync GEMM: C[M,N] = A[M,K] @ W[N,K]^T + bias, split-bf16 (3 passes).
// 128x128 tile, K-chunk 64 bf16, 256 threads = 8 warps (2m x 4n).
// ---------------------------------------------------------------------------
#define GEMM_SMEM 65536

__device__ __forceinline__ uint32_t tile_addr(uint32_t base, int row, int kb) {
    return base + row * 128 + ((((kb >> 4) ^ (row & 7))) << 4) + (kb & 15);
}

__global__ __launch_bounds__(256) void gemm_mma(
    const __nv_bfloat16* __restrict__ Ahi, const __nv_bfloat16* __restrict__ Alo,
    const __nv_bfloat16* __restrict__ Whi, const __nv_bfloat16* __restrict__ Wlo,
    const float* __restrict__ bias, float* __restrict__ C,
    int M, int N, int K)
{
    extern __shared__ char sm[];
    const uint32_t sb = smem_u32(sm);
    const uint32_t sAhi = sb, sAlo = sb + 16384, sBhi = sb + 32768, sBlo = sb + 49152;

    const int tid = threadIdx.x, lane = tid & 31, wid = tid >> 5;
    const int wm = (wid >> 2) * 64, wn = (wid & 3) * 32;
    const int bm = blockIdx.y * 128, bn = blockIdx.x * 128;

    const int aRow = lane & 15,                         aKb = (lane >> 4) * 16;
    const int bRow = (lane & 7) + ((lane >> 4) << 3),   bKb = ((lane >> 3) & 1) * 16;

    float acc[4][4][4];
#pragma unroll
    for (int i = 0; i < 4; i++)
#pragma unroll
        for (int j = 0; j < 4; j++)
#pragma unroll
            for (int r = 0; r < 4; r++) acc[i][j][r] = 0.f;

    for (int ch = 0; ch < K / 64; ch++) {
        const int k0 = ch * 64;
#pragma unroll
        for (int s = 0; s < 4; s++) {
            int idx = tid + s * 256;
            int r = idx >> 3, g = idx & 7;
            int so = r * 128 + ((g ^ (r & 7)) << 4);
            const size_t ga = (size_t)(bm + r) * K + k0 + g * 8;
            const size_t gb = (size_t)(bn + r) * K + k0 + g * 8;
            *(uint4*)(sm + so)         = *(const uint4*)(Ahi + ga);
            *(uint4*)(sm + 16384 + so) = *(const uint4*)(Alo + ga);
            *(uint4*)(sm + 32768 + so) = *(const uint4*)(Whi + gb);
            *(uint4*)(sm + 49152 + so) = *(const uint4*)(Wlo + gb);
        }
        __syncthreads();

#pragma unroll
        for (int ks = 0; ks < 4; ks++) {
            const int kb = ks * 32;
            uint32_t ah[4][4], bh[2][4];
#pragma unroll
            for (int mt = 0; mt < 4; mt++)
                LDSM4(ah[mt], tile_addr(sAhi, wm + mt * 16 + aRow, kb + aKb));
#pragma unroll
            for (int nt2 = 0; nt2 < 2; nt2++)
                LDSM4(bh[nt2], tile_addr(sBhi, wn + nt2 * 16 + bRow, kb + bKb));
#pragma unroll
            for (int mt = 0; mt < 4; mt++)
#pragma unroll
                for (int nt = 0; nt < 4; nt++)
                    MMA_BF16(acc[mt][nt], ah[mt], &bh[nt >> 1][(nt & 1) * 2]);

            uint32_t al[4][4];
#pragma unroll
            for (int mt = 0; mt < 4; mt++)
                LDSM4(al[mt], tile_addr(sAlo, wm + mt * 16 + aRow, kb + aKb));
#pragma unroll
            for (int mt = 0; mt < 4; mt++)
#pragma unroll
                for (int nt = 0; nt < 4; nt++)
                    MMA_BF16(acc[mt][nt], al[mt], &bh[nt >> 1][(nt & 1) * 2]);

            uint32_t bl[2][4];
#pragma unroll
            for (int nt2 = 0; nt2 < 2; nt2++)
                LDSM4(bl[nt2], tile_addr(sBlo, wn + nt2 * 16 + bRow, kb + bKb));
#pragma unroll
            for (int mt = 0; mt < 4; mt++)
#pragma unroll
                for (int nt = 0; nt < 4; nt++)
                    MMA_BF16(acc[mt][nt], ah[mt], &bl[nt >> 1][(nt & 1) * 2]);
        }
        __syncthreads();
    }

    const int r0 = lane >> 2, c0 = (lane & 3) * 2;
#pragma unroll
    for (int mt = 0; mt < 4; mt++) {
        int m = bm + wm + mt * 16 + r0;
#pragma unroll
        for (int nt = 0; nt < 4; nt++) {
            int n = bn + wn + nt * 8 + c0;
            float2 v0 = {acc[mt][nt][0] + bias[n], acc[mt][nt][1] + bias[n + 1]};
            float2 v1 = {acc[mt][nt][2] + bias[n], acc[mt][nt][3] + bias[n + 1]};
            *(float2*)&C[(size_t)m * N + n] = v0;
            *(float2*)&C[(size_t)(m + 8) * N + n] = v1;
        }
    }
}

// ---------------------------------------------------------------------------
// Fused attention, 128x128 tiles, 8x8 register blocking, fp32.
// __launch_bounds__(256,2): cap regs at 128 -> 2 CTAs/SM. unroll 2 keeps
// operand live-range at ~32 regs (no spills).
// ---------------------------------------------------------------------------
#define ATTN_SMEM 66560

__device__ __forceinline__ int sqz(int kk, int q) {
    return kk * 128 + (q ^ (((kk >> 2) & 15) << 2));
}

__global__ __launch_bounds__(256, 2) void attn_kernel(
    const float* __restrict__ Qp, const float* __restrict__ Kp,
    const float* __restrict__ Vp, float* __restrict__ attn,
    float* __restrict__ ctx)
{
    extern __shared__ float sf[];
    float* sQ  = sf;           // phase1: Q^T [64][128] swz
    float* sK  = sf + 8192;    // phase1: K^T [64][128] swz
    float* sPT = sf;           // phase2: P^T [64][128] swz
    float* sV  = sf + 8192;    // phase2: V [64][68]
    float* sM  = sf + 16384;   // [128]
    float* sL  = sf + 16512;   // [128] (inverse sums)

    const int b  = blockIdx.z;
    const int h  = blockIdx.y;
    const int q0 = blockIdx.x * 128;
    const int tid = threadIdx.x;
    const int tx = tid & 15, ty = tid >> 4;
    const int tx8 = tx * 8, ty8 = ty * 8;

    const float* Qbase = Qp + (size_t)b * SEQ * DMODEL + h * DK;
    const float* Kbase = Kp + (size_t)b * SEQ * DMODEL + h * DK;
    const float* Vbase = Vp + (size_t)b * SEQ * DMODEL + h * DK;
    float* attnBase = attn + ((size_t)(b * NHEADS + h)) * SEQ * SEQ;

#pragma unroll
    for (int s = 0; s < 8; s++) {
        int i = tid + s * 256;
        int r = i >> 4, c4 = (i & 15) * 4;
        float4 v = *(const float4*)&Qbase[(size_t)(q0 + r) * DMODEL + c4];
        sQ[sqz(c4 + 0, r)] = v.x;
        sQ[sqz(c4 + 1, r)] = v.y;
        sQ[sqz(c4 + 2, r)] = v.z;
        sQ[sqz(c4 + 3, r)] = v.w;
    }

    float m[8], l[8];
#pragma unroll
    for (int i = 0; i < 8; i++) { m[i] = -1e30f; l[i] = 0.f; }
    __syncthreads();

    const float scale = 0.125f; // 1/sqrt(64)

    // ---------------- Phase 1 ----------------
    for (int kt = 0; kt < SEQ / 128; kt++) {
#pragma unroll
        for (int s = 0; s < 8; s++) {
            int i = tid + s * 256;
            int r = i >> 4, c4 = (i & 15) * 4;
            float4 v = *(const float4*)&Kbase[(size_t)(kt * 128 + r) * DMODEL + c4];
            sK[sqz(c4 + 0, r)] = v.x;
            sK[sqz(c4 + 1, r)] = v.y;
            sK[sqz(c4 + 2, r)] = v.z;
            sK[sqz(c4 + 3, r)] = v.w;
        }
        __syncthreads();

        float s8[8][8];
#pragma unroll
        for (int i = 0; i < 8; i++)
#pragma unroll
            for (int j = 0; j < 8; j++) s8[i][j] = 0.f;

#pragma unroll 2
        for (int kk = 0; kk < DK; kk++) {
            float4 qa = *(const float4*)&sQ[sqz(kk, ty8)];
            float4 qb = *(const float4*)&sQ[sqz(kk, ty8 + 4)];
            float4 ka = *(const float4*)&sK[sqz(kk, tx8)];
            float4 kb = *(const float4*)&sK[sqz(kk, tx8 + 4)];
            float rq[8] = {qa.x, qa.y, qa.z, qa.w, qb.x, qb.y, qb.z, qb.w};
            float rk[8] = {ka.x, ka.y, ka.z, ka.w, kb.x, kb.y, kb.z, kb.w};
#pragma unroll
            for (int i = 0; i < 8; i++)
#pragma unroll
                for (int j = 0; j < 8; j++)
                    s8[i][j] = fmaf(rq[i], rk[j], s8[i][j]);
        }

#pragma unroll
        for (int i = 0; i < 8; i++) {
#pragma unroll
            for (int j = 0; j < 8; j++) s8[i][j] *= scale;
            float4 st0 = {s8[i][0], s8[i][1], s8[i][2], s8[i][3]};
            float4 st1 = {s8[i][4], s8[i][5], s8[i][6], s8[i][7]};
            float* dst = &attnBase[(size_t)(q0 + ty8 + i) * SEQ + kt * 128 + tx8];
            *(float4*)dst = st0;
            *(float4*)(dst + 4) = st1;
            float tm = s8[i][0];
#pragma unroll
            for (int j = 1; j < 8; j++) tm = fmaxf(tm, s8[i][j]);
#pragma unroll
            for (int off = 8; off >= 1; off >>= 1)
                tm = fmaxf(tm, __shfl_xor_sync(0xffffffffu, tm, off));
            float nm = fmaxf(m[i], tm);
            float rs = 0.f;
#pragma unroll
            for (int j = 0; j < 8; j++) rs += __expf(s8[i][j] - nm);
#pragma unroll
            for (int off = 8; off >= 1; off >>= 1)
                rs += __shfl_xor_sync(0xffffffffu, rs, off);
            l[i] = l[i] * __expf(m[i] - nm) + rs;
            m[i] = nm;
        }
        __syncthreads();
    }

    if (tx == 0) {
#pragma unroll
        for (int i = 0; i < 8; i++) {
            sM[ty8 + i] = m[i];
            sL[ty8 + i] = 1.f / l[i];
        }
    }
    __syncthreads();

    // ---------------- Phase 2 ----------------
    const int tx2 = tid & 7, ty2 = tid >> 3;
    const int dk8 = tx2 * 8, qr4 = ty2 * 4;

    float o[4][8];
#pragma unroll
    for (int i = 0; i < 4; i++)
#pragma unroll
        for (int j = 0; j < 8; j++) o[i][j] = 0.f;

    for (int ck = 0; ck < SEQ / 64; ck++) {
#pragma unroll
        for (int s = 0; s < 4; s++) {
            int i = tid + s * 256;
            int r = i >> 4, c4 = (i & 15) * 4;
            float4 v = *(const float4*)&Vbase[(size_t)(ck * 64 + r) * DMODEL + c4];
            *(float4*)&sV[r * 68 + c4] = v;
        }
#pragma unroll
        for (int s = 0; s < 8; s++) {
            int i = tid + s * 256;
            int qq = i >> 4, k4 = (i & 15) * 4;
            float* gp = &attnBase[(size_t)(q0 + qq) * SEQ + ck * 64 + k4];
            float4 sv = *(const float4*)gp;
            float mq = sM[qq], il = sL[qq];
            float p0 = __expf(sv.x - mq) * il;
            float p1 = __expf(sv.y - mq) * il;
            float p2 = __expf(sv.z - mq) * il;
            float p3 = __expf(sv.w - mq) * il;
            float4 pv = {p0, p1, p2, p3};
            *(float4*)gp = pv;
            sPT[sqz(k4 + 0, qq)] = p0;
            sPT[sqz(k4 + 1, qq)] = p1;
            sPT[sqz(k4 + 2, qq)] = p2;
            sPT[sqz(k4 + 3, qq)] = p3;
        }
        __syncthreads();

#pragma unroll 2
        for (int kk = 0; kk < 64; kk++) {
            float4 pa = *(const float4*)&sPT[sqz(kk, qr4)];
            float4 va = *(const float4*)&sV[kk * 68 + dk8];
            float4 vb = *(const float4*)&sV[kk * 68 + dk8 + 4];
            float rp[4] = {pa.x, pa.y, pa.z, pa.w};
            float rv[8] = {va.x, va.y, va.z, va.w, vb.x, vb.y, vb.z, vb.w};
#pragma unroll
            for (int i = 0; i < 4; i++)
#pragma unroll
                for (int j = 0; j < 8; j++)
                    o[i][j] = fmaf(rp[i], rv[j], o[i][j]);
        }
        __syncthreads();
    }

    float* ctxBase = ctx + (size_t)b * SEQ * DMODEL + h * DK;
#pragma unroll
    for (int i = 0; i < 4; i++) {
        float4 o0 = {o[i][0], o[i][1], o[i][2], o[i][3]};
        float4 o1 = {o[i][4], o[i][5], o[i][6], o[i][7]};
        float* dst = &ctxBase[(size_t)(q0 + qr4 + i) * DMODEL + dk8];
        *(float4*)dst = o0;
        *(float4*)(dst + 4) = o1;
    }
}

// ---------------------------------------------------------------------------
extern "C" void kernel_launch(void* const* d_in, const int* in_sizes, int n_in,
                              void* d_out, int out_size)
{
    const float* q  = (const float*)d_in[0];
    const float* k  = (const float*)d_in[1];
    const float* v  = (const float*)d_in[2];
    const float* wq = (const float*)d_in[3];
    const float* bq = (const float*)d_in[4];
    const float* wk = (const float*)d_in[5];
    const float* bk = (const float*)d_in[6];
    const float* wv = (const float*)d_in[7];
    const float* bv = (const float*)d_in[8];
    const float* wo = (const float*)d_in[9];
    const float* bo = (const float*)d_in[10];

    float* out  = (float*)d_out;
    float* attn = out + (size_t)MROWS * DMODEL;

    float *Qp, *Kp, *Vp, *ctx;
    __nv_bfloat16 *A1h, *A1l, *A2h, *A2l, *A3h, *A3l, *W1h, *W1l, *W2h, *W2l;
    cudaGetSymbolAddress((void**)&Qp,  g_Qp);
    cudaGetSymbolAddress((void**)&Kp,  g_Kp);
    cudaGetSymbolAddress((void**)&Vp,  g_Vp);
    cudaGetSymbolAddress((void**)&ctx, g_ctx);
    cudaGetSymbolAddress((void**)&A1h, g_A1hi); cudaGetSymbolAddress((void**)&A1l, g_A1lo);
    cudaGetSymbolAddress((void**)&A2h, g_A2hi); cudaGetSymbolAddress((void**)&A2l, g_A2lo);
    cudaGetSymbolAddress((void**)&A3h, g_A3hi); cudaGetSymbolAddress((void**)&A3l, g_A3lo);
    cudaGetSymbolAddress((void**)&W1h, g_W1hi); cudaGetSymbolAddress((void**)&W1l, g_W1lo);
    cudaGetSymbolAddress((void**)&W2h, g_W2hi); cudaGetSymbolAddress((void**)&W2l, g_W2lo);

    static int attr_set = 0;
    if (!attr_set) {
        cudaFuncSetAttribute(gemm_mma, cudaFuncAttributeMaxDynamicSharedMemorySize, GEMM_SMEM);
        cudaFuncSetAttribute(attn_kernel, cudaFuncAttributeMaxDynamicSharedMemorySize, ATTN_SMEM);
        attr_set = 1;
    }

    const int nA = MROWS * DMODEL;     // 4M
    const int nW = DMODEL * DMODEL;    // 1M
    dim3 cgA(nA / 4 / 256), cgW(nW / 4 / 256);
    dim3 ggrid(DMODEL / 128, MROWS / 128); // (8, 32)

    // Launch order puts gemm_mma at index 5 (ncu -s 5 -c 1 captures it).
    cvt_kernel<<<cgA, 256>>>(q,  A1h, A1l, nA);   // 0
    cvt_kernel<<<cgW, 256>>>(wq, W1h, W1l, nW);   // 1
    cvt_kernel<<<cgA, 256>>>(k,  A2h, A2l, nA);   // 2
    cvt_kernel<<<cgW, 256>>>(wk, W2h, W2l, nW);   // 3
    cvt_kernel<<<cgA, 256>>>(v,  A3h, A3l, nA);   // 4
    gemm_mma<<<ggrid, 256, GEMM_SMEM>>>(A1h, A1l, W1h, W1l, bq, Qp, MROWS, DMODEL, DMODEL); // 5
    cvt_kernel<<<cgW, 256>>>(wv, W1h, W1l, nW);   // 6 (W1 free after gemm Q)
    gemm_mma<<<ggrid, 256, GEMM_SMEM>>>(A2h, A2l, W2h, W2l, bk, Kp, MROWS, DMODEL, DMODEL); // 7
    gemm_mma<<<ggrid, 256, GEMM_SMEM>>>(A3h, A3l, W1h, W1l, bv, Vp, MROWS, DMODEL, DMODEL); // 8

    attn_kernel<<<dim3(SEQ / 128, NHEADS, BATCH), 256, ATTN_SMEM>>>(Qp, Kp, Vp, attn, ctx); // 9

    cvt_kernel<<<cgA, 256>>>(ctx, A1h, A1l, nA);  // 10
    cvt_kernel<<<cgW, 256>>>(wo,  W2h, W2l, nW);  // 11
    gemm_mma<<<ggrid, 256, GEMM_SMEM>>>(A1h, A1l, W2h, W2l, bo, out, MROWS, DMODEL, DMODEL); // 12
}

// round 9
// speedup vs baseline: 1.3027x; 1.0138x over previous
#include <cuda_runtime.h>
#include <cuda_bf16.h>
#include <stdint.h>

#define BATCH   2
#define SEQ     2048
#define DMODEL  1024
#define NHEADS  16
#define DK      64
#define MROWS   (BATCH*SEQ)      // 4096

// Scratch (__device__ globals: allocation-free rule)
__device__ float g_Qp[MROWS*DMODEL];
__device__ float g_Kp[MROWS*DMODEL];
__device__ float g_Vp[MROWS*DMODEL];
__device__ float g_ctx[MROWS*DMODEL];
__device__ __nv_bfloat16 g_A1hi[MROWS*DMODEL], g_A1lo[MROWS*DMODEL];
__device__ __nv_bfloat16 g_A2hi[MROWS*DMODEL], g_A2lo[MROWS*DMODEL];
__device__ __nv_bfloat16 g_A3hi[MROWS*DMODEL], g_A3lo[MROWS*DMODEL];
__device__ __nv_bfloat16 g_W1hi[DMODEL*DMODEL], g_W1lo[DMODEL*DMODEL];
__device__ __nv_bfloat16 g_W2hi[DMODEL*DMODEL], g_W2lo[DMODEL*DMODEL];
__device__ __nv_bfloat16 g_W3hi[DMODEL*DMODEL], g_W3lo[DMODEL*DMODEL];

__device__ __forceinline__ uint32_t smem_u32(const void* p) {
    uint32_t a;
    asm("{ .reg .u64 t; cvta.to.shared.u64 t, %1; cvt.u32.u64 %0, t; }" : "=r"(a) : "l"(p));
    return a;
}

#define LDSM4(r, addr) asm volatile( \
    "ldmatrix.sync.aligned.m8n8.x4.shared.b16 {%0,%1,%2,%3}, [%4];" \
    : "=r"((r)[0]), "=r"((r)[1]), "=r"((r)[2]), "=r"((r)[3]) : "r"(addr))

#define MMA_BF16(d, a, b) asm volatile( \
    "mma.sync.aligned.m16n8k16.row.col.f32.bf16.bf16.f32 " \
    "{%0,%1,%2,%3}, {%4,%5,%6,%7}, {%8,%9}, {%0,%1,%2,%3};" \
    : "+f"((d)[0]), "+f"((d)[1]), "+f"((d)[2]), "+f"((d)[3]) \
    : "r"((a)[0]), "r"((a)[1]), "r"((a)[2]), "r"((a)[3]), "r"((b)[0]), "r"((b)[1]))

__device__ __forceinline__ void cp16(uint32_t saddr, const void* g) {
    asm volatile("cp.async.cg.shared.global [%0], [%1], 16;" :: "r"(saddr), "l"(g));
}
#define CP_COMMIT() asm volatile("cp.async.commit_group;" ::: "memory")
#define CP_WAIT1()  asm volatile("cp.async.wait_group 1;" ::: "memory")
#define CP_WAIT0()  asm volatile("cp.async.wait_group 0;" ::: "memory")

// ---------------------------------------------------------------------------
// fp32 -> (hi, lo) bf16 split
// ---------------------------------------------------------------------------
__global__ __launch_bounds__(256) void cvt_kernel(
    const float* __restrict__ x, __nv_bfloat16* __restrict__ hi,
    __nv_bfloat16* __restrict__ lo, int n)
{
    int i = (blockIdx.x * 256 + threadIdx.x) * 4;
    if (i >= n) return;
    float4 v = *(const float4*)(x + i);
    __nv_bfloat16 h0 = __float2bfloat16(v.x), h1 = __float2bfloat16(v.y);
    __nv_bfloat16 h2 = __float2bfloat16(v.z), h3 = __float2bfloat16(v.w);
    *(__nv_bfloat162*)(hi + i)     = __halves2bfloat162(h0, h1);
    *(__nv_bfloat162*)(hi + i + 2) = __halves2bfloat162(h2, h3);
    *(__nv_bfloat162*)(lo + i)     = __floats2bfloat162_rn(
        v.x - __bfloat162float(h0), v.y - __bfloat162float(h1));
    *(__nv_bfloat162*)(lo + i + 2) = __floats2bfloat162_rn(
        v.z - __bfloat162float(h2), v.w - __bfloat162float(h3));
}

// ---------------------------------------------------------------------------
// mma.sync GEMM: C = A @ W^T + bias, split-bf16 (3 passes), 2-stage cp.async
// pipeline. 128x128 tile, K-chunk 64, 256 threads = 8 warps (2m x 4n).
// ---------------------------------------------------------------------------
#define STG        65536
#define GEMM_SMEM  (2*STG)

__device__ __forceinline__ uint32_t tile_addr(uint32_t base, int row, int kb) {
    return base + row * 128 + ((((kb >> 4) ^ (row & 7))) << 4) + (kb & 15);
}

__global__ __launch_bounds__(256) void gemm_mma(
    const __nv_bfloat16* __restrict__ Ahi, const __nv_bfloat16* __restrict__ Alo,
    const __nv_bfloat16* __restrict__ Whi, const __nv_bfloat16* __restrict__ Wlo,
    const float* __restrict__ bias, float* __restrict__ C,
    int M, int N, int K)
{
    extern __shared__ char sm[];
    const uint32_t sb = smem_u32(sm);

    const int tid = threadIdx.x, lane = tid & 31, wid = tid >> 5;
    const int wm = (wid >> 2) * 64, wn = (wid & 3) * 32;
    const int bm = blockIdx.y * 128, bn = blockIdx.x * 128;

    const int aRow = lane & 15,                         aKb = (lane >> 4) * 16;
    const int bRow = (lane & 7) + ((lane >> 4) << 3),   bKb = ((lane >> 3) & 1) * 16;

    // per-thread load geometry (same for every chunk)
    const int lr = tid >> 3, lg = tid & 7;  // handles s-stride below

    float acc[4][4][4];
#pragma unroll
    for (int i = 0; i < 4; i++)
#pragma unroll
        for (int j = 0; j < 4; j++)
#pragma unroll
            for (int r = 0; r < 4; r++) acc[i][j][r] = 0.f;

    const int nCh = K / 64;

    // ---- async chunk loader: 64KB (4 tiles) into stage st ----
    auto load_chunk = [&](int ch, int st) {
        const int k0 = ch * 64;
        const uint32_t stg = sb + st * STG;
#pragma unroll
        for (int s = 0; s < 4; s++) {
            int idx = tid + s * 256;
            int r = idx >> 3, g = idx & 7;
            uint32_t so = r * 128 + ((g ^ (r & 7)) << 4);
            const size_t ga = (size_t)(bm + r) * K + k0 + g * 8;
            const size_t gb = (size_t)(bn + r) * K + k0 + g * 8;
            cp16(stg + so,         Ahi + ga);
            cp16(stg + 16384 + so, Alo + ga);
            cp16(stg + 32768 + so, Whi + gb);
            cp16(stg + 49152 + so, Wlo + gb);
        }
        CP_COMMIT();
    };

    load_chunk(0, 0);

    for (int ch = 0; ch < nCh; ch++) {
        if (ch + 1 < nCh) { load_chunk(ch + 1, (ch + 1) & 1); CP_WAIT1(); }
        else              { CP_WAIT0(); }
        __syncthreads();

        const uint32_t stg  = sb + (ch & 1) * STG;
        const uint32_t sAhi = stg, sAlo = stg + 16384;
        const uint32_t sBhi = stg + 32768, sBlo = stg + 49152;

#pragma unroll
        for (int ks = 0; ks < 4; ks++) {
            const int kb = ks * 32;
            uint32_t ah[4][4], bh[2][4];
#pragma unroll
            for (int mt = 0; mt < 4; mt++)
                LDSM4(ah[mt], tile_addr(sAhi, wm + mt * 16 + aRow, kb + aKb));
#pragma unroll
            for (int nt2 = 0; nt2 < 2; nt2++)
                LDSM4(bh[nt2], tile_addr(sBhi, wn + nt2 * 16 + bRow, kb + bKb));
#pragma unroll
            for (int mt = 0; mt < 4; mt++)
#pragma unroll
                for (int nt = 0; nt < 4; nt++)
                    MMA_BF16(acc[mt][nt], ah[mt], &bh[nt >> 1][(nt & 1) * 2]);

            uint32_t al[4][4];
#pragma unroll
            for (int mt = 0; mt < 4; mt++)
                LDSM4(al[mt], tile_addr(sAlo, wm + mt * 16 + aRow, kb + aKb));
#pragma unroll
            for (int mt = 0; mt < 4; mt++)
#pragma unroll
                for (int nt = 0; nt < 4; nt++)
                    MMA_BF16(acc[mt][nt], al[mt], &bh[nt >> 1][(nt & 1) * 2]);

            uint32_t bl[2][4];
#pragma unroll
            for (int nt2 = 0; nt2 < 2; nt2++)
                LDSM4(bl[nt2], tile_addr(sBlo, wn + nt2 * 16 + bRow, kb + bKb));
#pragma unroll
            for (int mt = 0; mt < 4; mt++)
#pragma unroll
                for (int nt = 0; nt < 4; nt++)
                    MMA_BF16(acc[mt][nt], ah[mt], &bl[nt >> 1][(nt & 1) * 2]);
        }
        __syncthreads();
    }

    const int r0 = lane >> 2, c0 = (lane & 3) * 2;
#pragma unroll
    for (int mt = 0; mt < 4; mt++) {
        int m = bm + wm + mt * 16 + r0;
#pragma unroll
        for (int nt = 0; nt < 4; nt++) {
            int n = bn + wn + nt * 8 + c0;
            float2 v0 = {acc[mt][nt][0] + bias[n], acc[mt][nt][1] + bias[n + 1]};
            float2 v1 = {acc[mt][nt][2] + bias[n], acc[mt][nt][3] + bias[n + 1]};
            *(float2*)&C[(size_t)m * N + n] = v0;
            *(float2*)&C[(size_t)(m + 8) * N + n] = v1;
        }
    }
}

// ---------------------------------------------------------------------------
// Fused attention (unchanged from R8 passing version)
// ---------------------------------------------------------------------------
#define ATTN_SMEM 66560

__device__ __forceinline__ int sqz(int kk, int q) {
    return kk * 128 + (q ^ (((kk >> 2) & 15) << 2));
}

__global__ __launch_bounds__(256, 2) void attn_kernel(
    const float* __restrict__ Qp, const float* __restrict__ Kp,
    const float* __restrict__ Vp, float* __restrict__ attn,
    float* __restrict__ ctx)
{
    extern __shared__ float sf[];
    float* sQ  = sf;
    float* sK  = sf + 8192;
    float* sPT = sf;
    float* sV  = sf + 8192;
    float* sM  = sf + 16384;
    float* sL  = sf + 16512;

    const int b  = blockIdx.z;
    const int h  = blockIdx.y;
    const int q0 = blockIdx.x * 128;
    const int tid = threadIdx.x;
    const int tx = tid & 15, ty = tid >> 4;
    const int tx8 = tx * 8, ty8 = ty * 8;

    const float* Qbase = Qp + (size_t)b * SEQ * DMODEL + h * DK;
    const float* Kbase = Kp + (size_t)b * SEQ * DMODEL + h * DK;
    const float* Vbase = Vp + (size_t)b * SEQ * DMODEL + h * DK;
    float* attnBase = attn + ((size_t)(b * NHEADS + h)) * SEQ * SEQ;

#pragma unroll
    for (int s = 0; s < 8; s++) {
        int i = tid + s * 256;
        int r = i >> 4, c4 = (i & 15) * 4;
        float4 v = *(const float4*)&Qbase[(size_t)(q0 + r) * DMODEL + c4];
        sQ[sqz(c4 + 0, r)] = v.x;
        sQ[sqz(c4 + 1, r)] = v.y;
        sQ[sqz(c4 + 2, r)] = v.z;
        sQ[sqz(c4 + 3, r)] = v.w;
    }

    float m[8], l[8];
#pragma unroll
    for (int i = 0; i < 8; i++) { m[i] = -1e30f; l[i] = 0.f; }
    __syncthreads();

    const float scale = 0.125f;

    for (int kt = 0; kt < SEQ / 128; kt++) {
#pragma unroll
        for (int s = 0; s < 8; s++) {
            int i = tid + s * 256;
            int r = i >> 4, c4 = (i & 15) * 4;
            float4 v = *(const float4*)&Kbase[(size_t)(kt * 128 + r) * DMODEL + c4];
            sK[sqz(c4 + 0, r)] = v.x;
            sK[sqz(c4 + 1, r)] = v.y;
            sK[sqz(c4 + 2, r)] = v.z;
            sK[sqz(c4 + 3, r)] = v.w;
        }
        __syncthreads();

        float s8[8][8];
#pragma unroll
        for (int i = 0; i < 8; i++)
#pragma unroll
            for (int j = 0; j < 8; j++) s8[i][j] = 0.f;

#pragma unroll 2
        for (int kk = 0; kk < DK; kk++) {
            float4 qa = *(const float4*)&sQ[sqz(kk, ty8)];
            float4 qb = *(const float4*)&sQ[sqz(kk, ty8 + 4)];
            float4 ka = *(const float4*)&sK[sqz(kk, tx8)];
            float4 kb = *(const float4*)&sK[sqz(kk, tx8 + 4)];
            float rq[8] = {qa.x, qa.y, qa.z, qa.w, qb.x, qb.y, qb.z, qb.w};
            float rk[8] = {ka.x, ka.y, ka.z, ka.w, kb.x, kb.y, kb.z, kb.w};
#pragma unroll
            for (int i = 0; i < 8; i++)
#pragma unroll
                for (int j = 0; j < 8; j++)
                    s8[i][j] = fmaf(rq[i], rk[j], s8[i][j]);
        }

#pragma unroll
        for (int i = 0; i < 8; i++) {
#pragma unroll
            for (int j = 0; j < 8; j++) s8[i][j] *= scale;
            float4 st0 = {s8[i][0], s8[i][1], s8[i][2], s8[i][3]};
            float4 st1 = {s8[i][4], s8[i][5], s8[i][6], s8[i][7]};
            float* dst = &attnBase[(size_t)(q0 + ty8 + i) * SEQ + kt * 128 + tx8];
            *(float4*)dst = st0;
            *(float4*)(dst + 4) = st1;
            float tm = s8[i][0];
#pragma unroll
            for (int j = 1; j < 8; j++) tm = fmaxf(tm, s8[i][j]);
#pragma unroll
            for (int off = 8; off >= 1; off >>= 1)
                tm = fmaxf(tm, __shfl_xor_sync(0xffffffffu, tm, off));
            float nm = fmaxf(m[i], tm);
            float rs = 0.f;
#pragma unroll
            for (int j = 0; j < 8; j++) rs += __expf(s8[i][j] - nm);
#pragma unroll
            for (int off = 8; off >= 1; off >>= 1)
                rs += __shfl_xor_sync(0xffffffffu, rs, off);
            l[i] = l[i] * __expf(m[i] - nm) + rs;
            m[i] = nm;
        }
        __syncthreads();
    }

    if (tx == 0) {
#pragma unroll
        for (int i = 0; i < 8; i++) {
            sM[ty8 + i] = m[i];
            sL[ty8 + i] = 1.f / l[i];
        }
    }
    __syncthreads();

    const int tx2 = tid & 7, ty2 = tid >> 3;
    const int dk8 = tx2 * 8, qr4 = ty2 * 4;

    float o[4][8];
#pragma unroll
    for (int i = 0; i < 4; i++)
#pragma unroll
        for (int j = 0; j < 8; j++) o[i][j] = 0.f;

    for (int ck = 0; ck < SEQ / 64; ck++) {
#pragma unroll
        for (int s = 0; s < 4; s++) {
            int i = tid + s * 256;
            int r = i >> 4, c4 = (i & 15) * 4;
            float4 v = *(const float4*)&Vbase[(size_t)(ck * 64 + r) * DMODEL + c4];
            *(float4*)&sV[r * 68 + c4] = v;
        }
#pragma unroll
        for (int s = 0; s < 8; s++) {
            int i = tid + s * 256;
            int qq = i >> 4, k4 = (i & 15) * 4;
            float* gp = &attnBase[(size_t)(q0 + qq) * SEQ + ck * 64 + k4];
            float4 sv = *(const float4*)gp;
            float mq = sM[qq], il = sL[qq];
            float p0 = __expf(sv.x - mq) * il;
            float p1 = __expf(sv.y - mq) * il;
            float p2 = __expf(sv.z - mq) * il;
            float p3 = __expf(sv.w - mq) * il;
            float4 pv = {p0, p1, p2, p3};
            *(float4*)gp = pv;
            sPT[sqz(k4 + 0, qq)] = p0;
            sPT[sqz(k4 + 1, qq)] = p1;
            sPT[sqz(k4 + 2, qq)] = p2;
            sPT[sqz(k4 + 3, qq)] = p3;
        }
        __syncthreads();

#pragma unroll 2
        for (int kk = 0; kk < 64; kk++) {
            float4 pa = *(const float4*)&sPT[sqz(kk, qr4)];
            float4 va = *(const float4*)&sV[kk * 68 + dk8];
            float4 vb = *(const float4*)&sV[kk * 68 + dk8 + 4];
            float rp[4] = {pa.x, pa.y, pa.z, pa.w};
            float rv[8] = {va.x, va.y, va.z, va.w, vb.x, vb.y, vb.z, vb.w};
#pragma unroll
            for (int i = 0; i < 4; i++)
#pragma unroll
                for (int j = 0; j < 8; j++)
                    o[i][j] = fmaf(rp[i], rv[j], o[i][j]);
        }
        __syncthreads();
    }

    float* ctxBase = ctx + (size_t)b * SEQ * DMODEL + h * DK;
#pragma unroll
    for (int i = 0; i < 4; i++) {
        float4 o0 = {o[i][0], o[i][1], o[i][2], o[i][3]};
        float4 o1 = {o[i][4], o[i][5], o[i][6], o[i][7]};
        float* dst = &ctxBase[(size_t)(q0 + qr4 + i) * DMODEL + dk8];
        *(float4*)dst = o0;
        *(float4*)(dst + 4) = o1;
    }
}

// ---------------------------------------------------------------------------
extern "C" void kernel_launch(void* const* d_in, const int* in_sizes, int n_in,
                              void* d_out, int out_size)
{
    const float* q  = (const float*)d_in[0];
    const float* k  = (const float*)d_in[1];
    const float* v  = (const float*)d_in[2];
    const float* wq = (const float*)d_in[3];
    const float* bq = (const float*)d_in[4];
    const float* wk = (const float*)d_in[5];
    const float* bk = (const float*)d_in[6];
    const float* wv = (const float*)d_in[7];
    const float* bv = (const float*)d_in[8];
    const float* wo = (const float*)d_in[9];
    const float* bo = (const float*)d_in[10];

    float* out  = (float*)d_out;
    float* attn = out + (size_t)MROWS * DMODEL;

    float *Qp, *Kp, *Vp, *ctx;
    __nv_bfloat16 *A1h, *A1l, *A2h, *A2l, *A3h, *A3l;
    __nv_bfloat16 *W1h, *W1l, *W2h, *W2l, *W3h, *W3l;
    cudaGetSymbolAddress((void**)&Qp,  g_Qp);
    cudaGetSymbolAddress((void**)&Kp,  g_Kp);
    cudaGetSymbolAddress((void**)&Vp,  g_Vp);
    cudaGetSymbolAddress((void**)&ctx, g_ctx);
    cudaGetSymbolAddress((void**)&A1h, g_A1hi); cudaGetSymbolAddress((void**)&A1l, g_A1lo);
    cudaGetSymbolAddress((void**)&A2h, g_A2hi); cudaGetSymbolAddress((void**)&A2l, g_A2lo);
    cudaGetSymbolAddress((void**)&A3h, g_A3hi); cudaGetSymbolAddress((void**)&A3l, g_A3lo);
    cudaGetSymbolAddress((void**)&W1h, g_W1hi); cudaGetSymbolAddress((void**)&W1l, g_W1lo);
    cudaGetSymbolAddress((void**)&W2h, g_W2hi); cudaGetSymbolAddress((void**)&W2l, g_W2lo);
    cudaGetSymbolAddress((void**)&W3h, g_W3hi); cudaGetSymbolAddress((void**)&W3l, g_W3lo);

    static int attr_set = 0;
    if (!attr_set) {
        cudaFuncSetAttribute(gemm_mma, cudaFuncAttributeMaxDynamicSharedMemorySize, GEMM_SMEM);
        cudaFuncSetAttribute(attn_kernel, cudaFuncAttributeMaxDynamicSharedMemorySize, ATTN_SMEM);
        attr_set = 1;
    }

    const int nA = MROWS * DMODEL;     // 4M
    const int nW = DMODEL * DMODEL;    // 1M
    dim3 cgA(nA / 4 / 256), cgW(nW / 4 / 256);
    dim3 ggrid(DMODEL / 128, MROWS / 128); // (8, 32)

    // Launch order: index 6 is gemm_mma (empirically, ncu captures launch #6).
    cvt_kernel<<<cgA, 256>>>(q,  A1h, A1l, nA);   // 0
    cvt_kernel<<<cgW, 256>>>(wq, W1h, W1l, nW);   // 1
    cvt_kernel<<<cgA, 256>>>(k,  A2h, A2l, nA);   // 2
    cvt_kernel<<<cgW, 256>>>(wk, W2h, W2l, nW);   // 3
    cvt_kernel<<<cgA, 256>>>(v,  A3h, A3l, nA);   // 4
    cvt_kernel<<<cgW, 256>>>(wv, W3h, W3l, nW);   // 5
    gemm_mma<<<ggrid, 256, GEMM_SMEM>>>(A1h, A1l, W1h, W1l, bq, Qp, MROWS, DMODEL, DMODEL); // 6
    gemm_mma<<<ggrid, 256, GEMM_SMEM>>>(A2h, A2l, W2h, W2l, bk, Kp, MROWS, DMODEL, DMODEL); // 7
    gemm_mma<<<ggrid, 256, GEMM_SMEM>>>(A3h, A3l, W3h, W3l, bv, Vp, MROWS, DMODEL, DMODEL); // 8

    attn_kernel<<<dim3(SEQ / 128, NHEADS, BATCH), 256, ATTN_SMEM>>>(Qp, Kp, Vp, attn, ctx); // 9

    cvt_kernel<<<cgA, 256>>>(ctx, A1h, A1l, nA);  // 10
    cvt_kernel<<<cgW, 256>>>(wo,  W1h, W1l, nW);  // 11
    gemm_mma<<<ggrid, 256, GEMM_SMEM>>>(A1h, A1l, W1h, W1l, bo, out, MROWS, DMODEL, DMODEL); // 12
}

// round 10
// speedup vs baseline: 1.3755x; 1.0559x over previous
#include <cuda_runtime.h>
#include <cuda_bf16.h>
#include <stdint.h>

#define BATCH   2
#define SEQ     2048
#define DMODEL  1024
#define NHEADS  16
#define DK      64
#define MROWS   (BATCH*SEQ)      // 4096

// Scratch (__device__ globals: allocation-free rule)
__device__ float g_Qp[MROWS*DMODEL];
__device__ float g_Kp[MROWS*DMODEL];
__device__ float g_Vp[MROWS*DMODEL];
__device__ float g_ctx[MROWS*DMODEL];
__device__ __nv_bfloat16 g_A1hi[MROWS*DMODEL], g_A1lo[MROWS*DMODEL];
__device__ __nv_bfloat16 g_A2hi[MROWS*DMODEL], g_A2lo[MROWS*DMODEL];
__device__ __nv_bfloat16 g_A3hi[MROWS*DMODEL], g_A3lo[MROWS*DMODEL];
__device__ __nv_bfloat16 g_W1hi[DMODEL*DMODEL], g_W1lo[DMODEL*DMODEL];
__device__ __nv_bfloat16 g_W2hi[DMODEL*DMODEL], g_W2lo[DMODEL*DMODEL];
__device__ __nv_bfloat16 g_W3hi[DMODEL*DMODEL], g_W3lo[DMODEL*DMODEL];

__device__ __forceinline__ uint32_t smem_u32(const void* p) {
    uint32_t a;
    asm("{ .reg .u64 t; cvta.to.shared.u64 t, %1; cvt.u32.u64 %0, t; }" : "=r"(a) : "l"(p));
    return a;
}

#define LDSM4(r, addr) asm volatile( \
    "ldmatrix.sync.aligned.m8n8.x4.shared.b16 {%0,%1,%2,%3}, [%4];" \
    : "=r"((r)[0]), "=r"((r)[1]), "=r"((r)[2]), "=r"((r)[3]) : "r"(addr))

#define MMA_BF16(d, a, b) asm volatile( \
    "mma.sync.aligned.m16n8k16.row.col.f32.bf16.bf16.f32 " \
    "{%0,%1,%2,%3}, {%4,%5,%6,%7}, {%8,%9}, {%0,%1,%2,%3};" \
    : "+f"((d)[0]), "+f"((d)[1]), "+f"((d)[2]), "+f"((d)[3]) \
    : "r"((a)[0]), "r"((a)[1]), "r"((a)[2]), "r"((a)[3]), "r"((b)[0]), "r"((b)[1]))

__device__ __forceinline__ void cp16(uint32_t saddr, const void* g) {
    asm volatile("cp.async.cg.shared.global [%0], [%1], 16;" :: "r"(saddr), "l"(g));
}
#define CP_COMMIT() asm volatile("cp.async.commit_group;" ::: "memory")
#define CP_WAIT1()  asm volatile("cp.async.wait_group 1;" ::: "memory")
#define CP_WAIT0()  asm volatile("cp.async.wait_group 0;" ::: "memory")

// ---------------------------------------------------------------------------
// fp32 -> (hi, lo) bf16 split
// ---------------------------------------------------------------------------
__global__ __launch_bounds__(256) void cvt_kernel(
    const float* __restrict__ x, __nv_bfloat16* __restrict__ hi,
    __nv_bfloat16* __restrict__ lo, int n)
{
    int i = (blockIdx.x * 256 + threadIdx.x) * 4;
    if (i >= n) return;
    float4 v = *(const float4*)(x + i);
    __nv_bfloat16 h0 = __float2bfloat16(v.x), h1 = __float2bfloat16(v.y);
    __nv_bfloat16 h2 = __float2bfloat16(v.z), h3 = __float2bfloat16(v.w);
    *(__nv_bfloat162*)(hi + i)     = __halves2bfloat162(h0, h1);
    *(__nv_bfloat162*)(hi + i + 2) = __halves2bfloat162(h2, h3);
    *(__nv_bfloat162*)(lo + i)     = __floats2bfloat162_rn(
        v.x - __bfloat162float(h0), v.y - __bfloat162float(h1));
    *(__nv_bfloat162*)(lo + i + 2) = __floats2bfloat162_rn(
        v.z - __bfloat162float(h2), v.w - __bfloat162float(h3));
}

// ---------------------------------------------------------------------------
// mma.sync GEMM: C = A @ W^T + bias, split-bf16 (3 passes), 2-stage cp.async
// pipeline. 128x128 tile, K-chunk 64, 256 threads = 8 warps (2m x 4n).
// ---------------------------------------------------------------------------
#define STG        65536
#define GEMM_SMEM  (2*STG)

__device__ __forceinline__ uint32_t tile_addr(uint32_t base, int row, int kb) {
    return base + row * 128 + ((((kb >> 4) ^ (row & 7))) << 4) + (kb & 15);
}

__global__ __launch_bounds__(256) void gemm_mma(
    const __nv_bfloat16* __restrict__ Ahi, const __nv_bfloat16* __restrict__ Alo,
    const __nv_bfloat16* __restrict__ Whi, const __nv_bfloat16* __restrict__ Wlo,
    const float* __restrict__ bias, float* __restrict__ C,
    int M, int N, int K)
{
    extern __shared__ char sm[];
    const uint32_t sb = smem_u32(sm);

    const int tid = threadIdx.x, lane = tid & 31, wid = tid >> 5;
    const int wm = (wid >> 2) * 64, wn = (wid & 3) * 32;
    const int bm = blockIdx.y * 128, bn = blockIdx.x * 128;

    const int aRow = lane & 15,                         aKb = (lane >> 4) * 16;
    const int bRow = (lane & 7) + ((lane >> 4) << 3),   bKb = ((lane >> 3) & 1) * 16;

    float acc[4][4][4];
#pragma unroll
    for (int i = 0; i < 4; i++)
#pragma unroll
        for (int j = 0; j < 4; j++)
#pragma unroll
            for (int r = 0; r < 4; r++) acc[i][j][r] = 0.f;

    const int nCh = K / 64;

    auto load_chunk = [&](int ch, int st) {
        const int k0 = ch * 64;
        const uint32_t stg = sb + st * STG;
#pragma unroll
        for (int s = 0; s < 4; s++) {
            int idx = tid + s * 256;
            int r = idx >> 3, g = idx & 7;
            uint32_t so = r * 128 + ((g ^ (r & 7)) << 4);
            const size_t ga = (size_t)(bm + r) * K + k0 + g * 8;
            const size_t gb = (size_t)(bn + r) * K + k0 + g * 8;
            cp16(stg + so,         Ahi + ga);
            cp16(stg + 16384 + so, Alo + ga);
            cp16(stg + 32768 + so, Whi + gb);
            cp16(stg + 49152 + so, Wlo + gb);
        }
        CP_COMMIT();
    };

    load_chunk(0, 0);

    for (int ch = 0; ch < nCh; ch++) {
        if (ch + 1 < nCh) { load_chunk(ch + 1, (ch + 1) & 1); CP_WAIT1(); }
        else              { CP_WAIT0(); }
        __syncthreads();

        const uint32_t stg  = sb + (ch & 1) * STG;
        const uint32_t sAhi = stg, sAlo = stg + 16384;
        const uint32_t sBhi = stg + 32768, sBlo = stg + 49152;

#pragma unroll
        for (int ks = 0; ks < 4; ks++) {
            const int kb = ks * 32;
            uint32_t ah[4][4], bh[2][4];
#pragma unroll
            for (int mt = 0; mt < 4; mt++)
                LDSM4(ah[mt], tile_addr(sAhi, wm + mt * 16 + aRow, kb + aKb));
#pragma unroll
            for (int nt2 = 0; nt2 < 2; nt2++)
                LDSM4(bh[nt2], tile_addr(sBhi, wn + nt2 * 16 + bRow, kb + bKb));
#pragma unroll
            for (int mt = 0; mt < 4; mt++)
#pragma unroll
                for (int nt = 0; nt < 4; nt++)
                    MMA_BF16(acc[mt][nt], ah[mt], &bh[nt >> 1][(nt & 1) * 2]);

            uint32_t al[4][4];
#pragma unroll
            for (int mt = 0; mt < 4; mt++)
                LDSM4(al[mt], tile_addr(sAlo, wm + mt * 16 + aRow, kb + aKb));
#pragma unroll
            for (int mt = 0; mt < 4; mt++)
#pragma unroll
                for (int nt = 0; nt < 4; nt++)
                    MMA_BF16(acc[mt][nt], al[mt], &bh[nt >> 1][(nt & 1) * 2]);

            uint32_t bl[2][4];
#pragma unroll
            for (int nt2 = 0; nt2 < 2; nt2++)
                LDSM4(bl[nt2], tile_addr(sBlo, wn + nt2 * 16 + bRow, kb + bKb));
#pragma unroll
            for (int mt = 0; mt < 4; mt++)
#pragma unroll
                for (int nt = 0; nt < 4; nt++)
                    MMA_BF16(acc[mt][nt], ah[mt], &bl[nt >> 1][(nt & 1) * 2]);
        }
        __syncthreads();
    }

    const int r0 = lane >> 2, c0 = (lane & 3) * 2;
#pragma unroll
    for (int mt = 0; mt < 4; mt++) {
        int m = bm + wm + mt * 16 + r0;
#pragma unroll
        for (int nt = 0; nt < 4; nt++) {
            int n = bn + wn + nt * 8 + c0;
            float2 v0 = {acc[mt][nt][0] + bias[n], acc[mt][nt][1] + bias[n + 1]};
            float2 v1 = {acc[mt][nt][2] + bias[n], acc[mt][nt][3] + bias[n + 1]};
            *(float2*)&C[(size_t)m * N + n] = v0;
            *(float2*)&C[(size_t)(m + 8) * N + n] = v1;
        }
    }
}

// ---------------------------------------------------------------------------
// Fused attention, exp-once scheme.
// Phase 1: p' = exp(s - nm_kt) stored into attn gmem, nm_kt per (row,tile)
//          in smem, online l/m.
// Phase 2: P = p' * fac[kt][row] where fac = exp(nm_kt - m_final)/l.
//          No exp in phase 2.
// ---------------------------------------------------------------------------
#define ATTN_SMEM 74752   // (8192 + 8192 + 128 + 128 + 2048) floats

__device__ __forceinline__ int sqz(int kk, int q) {
    return kk * 128 + (q ^ (((kk >> 2) & 15) << 2));
}

__global__ __launch_bounds__(256, 2) void attn_kernel(
    const float* __restrict__ Qp, const float* __restrict__ Kp,
    const float* __restrict__ Vp, float* __restrict__ attn,
    float* __restrict__ ctx)
{
    extern __shared__ float sf[];
    float* sQ  = sf;            // phase1: Q^T [64][128] swz
    float* sK  = sf + 8192;     // phase1: K^T [64][128] swz
    float* sPT = sf;            // phase2: P^T [64][128] swz
    float* sV  = sf + 8192;     // phase2: V [64][68]
    float* sM  = sf + 16384;    // [128] final row max
    float* sL  = sf + 16512;    // [128] 1/l
    float* sNM = sf + 16640;    // [16][128]: nm per tile -> fac per tile

    const int b  = blockIdx.z;
    const int h  = blockIdx.y;
    const int q0 = blockIdx.x * 128;
    const int tid = threadIdx.x;
    const int tx = tid & 15, ty = tid >> 4;
    const int tx8 = tx * 8, ty8 = ty * 8;

    const float* Qbase = Qp + (size_t)b * SEQ * DMODEL + h * DK;
    const float* Kbase = Kp + (size_t)b * SEQ * DMODEL + h * DK;
    const float* Vbase = Vp + (size_t)b * SEQ * DMODEL + h * DK;
    float* attnBase = attn + ((size_t)(b * NHEADS + h)) * SEQ * SEQ;

#pragma unroll
    for (int s = 0; s < 8; s++) {
        int i = tid + s * 256;
        int r = i >> 4, c4 = (i & 15) * 4;
        float4 v = *(const float4*)&Qbase[(size_t)(q0 + r) * DMODEL + c4];
        sQ[sqz(c4 + 0, r)] = v.x;
        sQ[sqz(c4 + 1, r)] = v.y;
        sQ[sqz(c4 + 2, r)] = v.z;
        sQ[sqz(c4 + 3, r)] = v.w;
    }

    float m[8], l[8];
#pragma unroll
    for (int i = 0; i < 8; i++) { m[i] = -1e30f; l[i] = 0.f; }
    __syncthreads();

    const float scale = 0.125f; // 1/sqrt(64)

    // ---------------- Phase 1 ----------------
    for (int kt = 0; kt < SEQ / 128; kt++) {
#pragma unroll
        for (int s = 0; s < 8; s++) {
            int i = tid + s * 256;
            int r = i >> 4, c4 = (i & 15) * 4;
            float4 v = *(const float4*)&Kbase[(size_t)(kt * 128 + r) * DMODEL + c4];
            sK[sqz(c4 + 0, r)] = v.x;
            sK[sqz(c4 + 1, r)] = v.y;
            sK[sqz(c4 + 2, r)] = v.z;
            sK[sqz(c4 + 3, r)] = v.w;
        }
        __syncthreads();

        float s8[8][8];
#pragma unroll
        for (int i = 0; i < 8; i++)
#pragma unroll
            for (int j = 0; j < 8; j++) s8[i][j] = 0.f;

#pragma unroll 2
        for (int kk = 0; kk < DK; kk++) {
            float4 qa = *(const float4*)&sQ[sqz(kk, ty8)];
            float4 qb = *(const float4*)&sQ[sqz(kk, ty8 + 4)];
            float4 ka = *(const float4*)&sK[sqz(kk, tx8)];
            float4 kb = *(const float4*)&sK[sqz(kk, tx8 + 4)];
            float rq[8] = {qa.x, qa.y, qa.z, qa.w, qb.x, qb.y, qb.z, qb.w};
            float rk[8] = {ka.x, ka.y, ka.z, ka.w, kb.x, kb.y, kb.z, kb.w};
#pragma unroll
            for (int i = 0; i < 8; i++)
#pragma unroll
                for (int j = 0; j < 8; j++)
                    s8[i][j] = fmaf(rq[i], rk[j], s8[i][j]);
        }

#pragma unroll
        for (int i = 0; i < 8; i++) {
#pragma unroll
            for (int j = 0; j < 8; j++) s8[i][j] *= scale;
            // row-tile max across the 16 tx lanes
            float tm = s8[i][0];
#pragma unroll
            for (int j = 1; j < 8; j++) tm = fmaxf(tm, s8[i][j]);
#pragma unroll
            for (int off = 8; off >= 1; off >>= 1)
                tm = fmaxf(tm, __shfl_xor_sync(0xffffffffu, tm, off));
            float nm = fmaxf(m[i], tm);
            // p' = exp(s - nm), store (exp-once), and row sum
            float p[8];
            float rs = 0.f;
#pragma unroll
            for (int j = 0; j < 8; j++) { p[j] = __expf(s8[i][j] - nm); rs += p[j]; }
            float4 st0 = {p[0], p[1], p[2], p[3]};
            float4 st1 = {p[4], p[5], p[6], p[7]};
            float* dst = &attnBase[(size_t)(q0 + ty8 + i) * SEQ + kt * 128 + tx8];
            *(float4*)dst = st0;
            *(float4*)(dst + 4) = st1;
#pragma unroll
            for (int off = 8; off >= 1; off >>= 1)
                rs += __shfl_xor_sync(0xffffffffu, rs, off);
            l[i] = l[i] * __expf(m[i] - nm) + rs;
            m[i] = nm;
            if (tx == 0) sNM[kt * 128 + ty8 + i] = nm;
        }
        __syncthreads();
    }

    // Publish final stats, then convert sNM -> fac table
    if (tx == 0) {
#pragma unroll
        for (int i = 0; i < 8; i++) {
            sM[ty8 + i] = m[i];
            sL[ty8 + i] = 1.f / l[i];
        }
    }
    __syncthreads();
    for (int i = tid; i < 16 * 128; i += 256) {
        int row = i & 127;
        sNM[i] = __expf(sNM[i] - sM[row]) * sL[row];
    }
    __syncthreads();

    // ---------------- Phase 2 (exp-free) ----------------
    const int tx2 = tid & 7, ty2 = tid >> 3;
    const int dk8 = tx2 * 8, qr4 = ty2 * 4;

    float o[4][8];
#pragma unroll
    for (int i = 0; i < 4; i++)
#pragma unroll
        for (int j = 0; j < 8; j++) o[i][j] = 0.f;

    for (int ck = 0; ck < SEQ / 64; ck++) {
        const float* facT = &sNM[(ck >> 1) * 128];
#pragma unroll
        for (int s = 0; s < 4; s++) {
            int i = tid + s * 256;
            int r = i >> 4, c4 = (i & 15) * 4;
            float4 v = *(const float4*)&Vbase[(size_t)(ck * 64 + r) * DMODEL + c4];
            *(float4*)&sV[r * 68 + c4] = v;
        }
#pragma unroll
        for (int s = 0; s < 8; s++) {
            int i = tid + s * 256;
            int qq = i >> 4, k4 = (i & 15) * 4;
            float* gp = &attnBase[(size_t)(q0 + qq) * SEQ + ck * 64 + k4];
            float4 sv = *(const float4*)gp;
            float fac = facT[qq];
            float p0 = sv.x * fac, p1 = sv.y * fac;
            float p2 = sv.z * fac, p3 = sv.w * fac;
            float4 pv = {p0, p1, p2, p3};
            *(float4*)gp = pv;
            sPT[sqz(k4 + 0, qq)] = p0;
            sPT[sqz(k4 + 1, qq)] = p1;
            sPT[sqz(k4 + 2, qq)] = p2;
            sPT[sqz(k4 + 3, qq)] = p3;
        }
        __syncthreads();

#pragma unroll 2
        for (int kk = 0; kk < 64; kk++) {
            float4 pa = *(const float4*)&sPT[sqz(kk, qr4)];
            float4 va = *(const float4*)&sV[kk * 68 + dk8];
            float4 vb = *(const float4*)&sV[kk * 68 + dk8 + 4];
            float rp[4] = {pa.x, pa.y, pa.z, pa.w};
            float rv[8] = {va.x, va.y, va.z, va.w, vb.x, vb.y, vb.z, vb.w};
#pragma unroll
            for (int i = 0; i < 4; i++)
#pragma unroll
                for (int j = 0; j < 8; j++)
                    o[i][j] = fmaf(rp[i], rv[j], o[i][j]);
        }
        __syncthreads();
    }

    float* ctxBase = ctx + (size_t)b * SEQ * DMODEL + h * DK;
#pragma unroll
    for (int i = 0; i < 4; i++) {
        float4 o0 = {o[i][0], o[i][1], o[i][2], o[i][3]};
        float4 o1 = {o[i][4], o[i][5], o[i][6], o[i][7]};
        float* dst = &ctxBase[(size_t)(q0 + qr4 + i) * DMODEL + dk8];
        *(float4*)dst = o0;
        *(float4*)(dst + 4) = o1;
    }
}

// ---------------------------------------------------------------------------
extern "C" void kernel_launch(void* const* d_in, const int* in_sizes, int n_in,
                              void* d_out, int out_size)
{
    const float* q  = (const float*)d_in[0];
    const float* k  = (const float*)d_in[1];
    const float* v  = (const float*)d_in[2];
    const float* wq = (const float*)d_in[3];
    const float* bq = (const float*)d_in[4];
    const float* wk = (const float*)d_in[5];
    const float* bk = (const float*)d_in[6];
    const float* wv = (const float*)d_in[7];
    const float* bv = (const float*)d_in[8];
    const float* wo = (const float*)d_in[9];
    const float* bo = (const float*)d_in[10];

    float* out  = (float*)d_out;
    float* attn = out + (size_t)MROWS * DMODEL;

    float *Qp, *Kp, *Vp, *ctx;
    __nv_bfloat16 *A1h, *A1l, *A2h, *A2l, *A3h, *A3l;
    __nv_bfloat16 *W1h, *W1l, *W2h, *W2l, *W3h, *W3l;
    cudaGetSymbolAddress((void**)&Qp,  g_Qp);
    cudaGetSymbolAddress((void**)&Kp,  g_Kp);
    cudaGetSymbolAddress((void**)&Vp,  g_Vp);
    cudaGetSymbolAddress((void**)&ctx, g_ctx);
    cudaGetSymbolAddress((void**)&A1h, g_A1hi); cudaGetSymbolAddress((void**)&A1l, g_A1lo);
    cudaGetSymbolAddress((void**)&A2h, g_A2hi); cudaGetSymbolAddress((void**)&A2l, g_A2lo);
    cudaGetSymbolAddress((void**)&A3h, g_A3hi); cudaGetSymbolAddress((void**)&A3l, g_A3lo);
    cudaGetSymbolAddress((void**)&W1h, g_W1hi); cudaGetSymbolAddress((void**)&W1l, g_W1lo);
    cudaGetSymbolAddress((void**)&W2h, g_W2hi); cudaGetSymbolAddress((void**)&W2l, g_W2lo);
    cudaGetSymbolAddress((void**)&W3h, g_W3hi); cudaGetSymbolAddress((void**)&W3l, g_W3lo);

    static int attr_set = 0;
    if (!attr_set) {
        cudaFuncSetAttribute(gemm_mma, cudaFuncAttributeMaxDynamicSharedMemorySize, GEMM_SMEM);
        cudaFuncSetAttribute(attn_kernel, cudaFuncAttributeMaxDynamicSharedMemorySize, ATTN_SMEM);
        attr_set = 1;
    }

    const int nA = MROWS * DMODEL;     // 4M
    const int nW = DMODEL * DMODEL;    // 1M
    dim3 cgA(nA / 4 / 256), cgW(nW / 4 / 256);
    dim3 ggrid(DMODEL / 128, MROWS / 128); // (8, 32)

    // Launches 5 AND 6 are both gemm_mma: whichever index ncu captures
    // (it has shown both conventions), next profile lands on a GEMM.
    cvt_kernel<<<cgA, 256>>>(q,  A1h, A1l, nA);   // 0
    cvt_kernel<<<cgW, 256>>>(wq, W1h, W1l, nW);   // 1
    cvt_kernel<<<cgA, 256>>>(k,  A2h, A2l, nA);   // 2
    cvt_kernel<<<cgW, 256>>>(wk, W2h, W2l, nW);   // 3
    cvt_kernel<<<cgA, 256>>>(v,  A3h, A3l, nA);   // 4
    gemm_mma<<<ggrid, 256, GEMM_SMEM>>>(A1h, A1l, W1h, W1l, bq, Qp, MROWS, DMODEL, DMODEL); // 5
    gemm_mma<<<ggrid, 256, GEMM_SMEM>>>(A2h, A2l, W2h, W2l, bk, Kp, MROWS, DMODEL, DMODEL); // 6
    cvt_kernel<<<cgW, 256>>>(wv, W3h, W3l, nW);   // 7
    gemm_mma<<<ggrid, 256, GEMM_SMEM>>>(A3h, A3l, W3h, W3l, bv, Vp, MROWS, DMODEL, DMODEL); // 8

    attn_kernel<<<dim3(SEQ / 128, NHEADS, BATCH), 256, ATTN_SMEM>>>(Qp, Kp, Vp, attn, ctx); // 9

    cvt_kernel<<<cgA, 256>>>(ctx, A1h, A1l, nA);  // 10
    cvt_kernel<<<cgW, 256>>>(wo,  W1h, W1l, nW);  // 11
    gemm_mma<<<ggrid, 256, GEMM_SMEM>>>(A1h, A1l, W1h, W1l, bo, out, MROWS, DMODEL, DMODEL); // 12
}

// round 13
// speedup vs baseline: 1.7213x; 1.2514x over previous
#include <cuda_runtime.h>
#include <cuda_bf16.h>
#include <stdint.h>

#define BATCH   2
#define SEQ     2048
#define DMODEL  1024
#define NHEADS  16
#define DK      64
#define MROWS   (BATCH*SEQ)      // 4096
typedef __nv_bfloat16  bf16;
typedef __nv_bfloat162 bf162;

// ---- scratch (__device__ globals: allocation-free rule) ----
__device__ bf16 g_Aqh[MROWS*DMODEL], g_Aql[MROWS*DMODEL];
__device__ bf16 g_Akh[MROWS*DMODEL], g_Akl[MROWS*DMODEL];
__device__ bf16 g_Avh[MROWS*DMODEL], g_Avl[MROWS*DMODEL];
__device__ bf16 g_Wqh[DMODEL*DMODEL], g_Wql[DMODEL*DMODEL];
__device__ bf16 g_Wkh[DMODEL*DMODEL], g_Wkl[DMODEL*DMODEL];
__device__ bf16 g_Wvh[DMODEL*DMODEL], g_Wvl[DMODEL*DMODEL];
__device__ bf16 g_Woh[DMODEL*DMODEL], g_Wol[DMODEL*DMODEL];
__device__ bf16 g_Qh[MROWS*DMODEL], g_Ql[MROWS*DMODEL];
__device__ bf16 g_Kh[MROWS*DMODEL], g_Kl[MROWS*DMODEL];
__device__ bf16 g_Vh[MROWS*DMODEL], g_Vl[MROWS*DMODEL];
__device__ bf16 g_Ch[MROWS*DMODEL], g_Cl[MROWS*DMODEL];

__device__ __forceinline__ uint32_t smem_u32(const void* p) {
    uint32_t a;
    asm("{ .reg .u64 t; cvta.to.shared.u64 t, %1; cvt.u32.u64 %0, t; }" : "=r"(a) : "l"(p));
    return a;
}

#define LDSM4(r, addr) asm volatile( \
    "ldmatrix.sync.aligned.m8n8.x4.shared.b16 {%0,%1,%2,%3}, [%4];" \
    : "=r"((r)[0]), "=r"((r)[1]), "=r"((r)[2]), "=r"((r)[3]) : "r"(addr))

#define MMA_BF16(d, a, b) asm volatile( \
    "mma.sync.aligned.m16n8k16.row.col.f32.bf16.bf16.f32 " \
    "{%0,%1,%2,%3}, {%4,%5,%6,%7}, {%8,%9}, {%0,%1,%2,%3};" \
    : "+f"((d)[0]), "+f"((d)[1]), "+f"((d)[2]), "+f"((d)[3]) \
    : "r"((a)[0]), "r"((a)[1]), "r"((a)[2]), "r"((a)[3]), "r"((b)[0]), "r"((b)[1]))

__device__ __forceinline__ void cp16(uint32_t saddr, const void* g) {
    asm volatile("cp.async.cg.shared.global [%0], [%1], 16;" :: "r"(saddr), "l"(g));
}
#define CP_COMMIT() asm volatile("cp.async.commit_group;" ::: "memory")
#define CP_WAIT1()  asm volatile("cp.async.wait_group 1;" ::: "memory")
#define CP_WAIT0()  asm volatile("cp.async.wait_group 0;" ::: "memory")

// 128B-row swizzled tile: byte offset of (row, kb bytes within 128B row)
__device__ __forceinline__ uint32_t off128(int row, int kb) {
    return row * 128 + ((((kb >> 4) ^ (row & 7)) & 7) << 4) + (kb & 15);
}

__device__ __forceinline__ void split_bf(float v, bf16& h, bf16& l) {
    h = __float2bfloat16(v);
    l = __float2bfloat16(v - __bfloat162float(h));
}

// ---------------------------------------------------------------------------
// cvt7: split 7 fp32 tensors (q,k,v 4M; wq,wk,wv,wo 1M) into bf16 hi/lo.
// ---------------------------------------------------------------------------
__global__ __launch_bounds__(256) void cvt7(
    const float* x0, const float* x1, const float* x2, const float* x3,
    const float* x4, const float* x5, const float* x6,
    bf16* h0, bf16* h1, bf16* h2, bf16* h3, bf16* h4, bf16* h5, bf16* h6,
    bf16* l0, bf16* l1, bf16* l2, bf16* l3, bf16* l4, bf16* l5, bf16* l6)
{
    const float* xs[7] = {x0, x1, x2, x3, x4, x5, x6};
    bf16* hs[7] = {h0, h1, h2, h3, h4, h5, h6};
    bf16* ls[7] = {l0, l1, l2, l3, l4, l5, l6};
    int t = blockIdx.y;
    int n = (t < 3) ? MROWS * DMODEL : DMODEL * DMODEL;
    int i = (blockIdx.x * 256 + threadIdx.x) * 4;
    if (i >= n) return;
    float4 v = *(const float4*)(xs[t] + i);
    bf16 a, b, c, d, e, f, g, h;
    split_bf(v.x, a, e); split_bf(v.y, b, f);
    split_bf(v.z, c, g); split_bf(v.w, d, h);
    *(bf162*)(hs[t] + i)     = __halves2bfloat162(a, b);
    *(bf162*)(hs[t] + i + 2) = __halves2bfloat162(c, d);
    *(bf162*)(ls[t] + i)     = __halves2bfloat162(e, f);
    *(bf162*)(ls[t] + i + 2) = __halves2bfloat162(g, h);
}

// ---------------------------------------------------------------------------
// mma.sync GEMM: 3-pass split-bf16, 2-stage cp.async. Output either fp32
// (C != null) or split bf16 (Chi/Clo).
// ---------------------------------------------------------------------------
#define STG       65536
#define GEMM_SMEM (2*STG)

__global__ __launch_bounds__(256) void gemm_mma(
    const bf16* __restrict__ Ahi, const bf16* __restrict__ Alo,
    const bf16* __restrict__ Whi, const bf16* __restrict__ Wlo,
    const float* __restrict__ bias, float* __restrict__ C,
    bf16* __restrict__ Chi, bf16* __restrict__ Clo,
    int M, int N, int K)
{
    extern __shared__ char sm[];
    const uint32_t sb = smem_u32(sm);
    const int tid = threadIdx.x, lane = tid & 31, wid = tid >> 5;
    const int wm = (wid >> 2) * 64, wn = (wid & 3) * 32;
    const int bm = blockIdx.y * 128, bn = blockIdx.x * 128;
    const int aRow = lane & 15,                       aKb = (lane >> 4) * 16;
    const int bRow = (lane & 7) + ((lane >> 4) << 3), bKb = ((lane >> 3) & 1) * 16;

    float acc[4][4][4];
#pragma unroll
    for (int i = 0; i < 4; i++)
#pragma unroll
        for (int j = 0; j < 4; j++)
#pragma unroll
            for (int r = 0; r < 4; r++) acc[i][j][r] = 0.f;

    const int nCh = K / 64;
    auto load_chunk = [&](int ch, int st) {
        const int k0 = ch * 64;
        const uint32_t stg = sb + st * STG;
#pragma unroll
        for (int s = 0; s < 4; s++) {
            int idx = tid + s * 256;
            int r = idx >> 3, g = idx & 7;
            uint32_t so = r * 128 + ((g ^ (r & 7)) << 4);
            const size_t ga = (size_t)(bm + r) * K + k0 + g * 8;
            const size_t gb = (size_t)(bn + r) * K + k0 + g * 8;
            cp16(stg + so,         Ahi + ga);
            cp16(stg + 16384 + so, Alo + ga);
            cp16(stg + 32768 + so, Whi + gb);
            cp16(stg + 49152 + so, Wlo + gb);
        }
        CP_COMMIT();
    };

    load_chunk(0, 0);
    for (int ch = 0; ch < nCh; ch++) {
        if (ch + 1 < nCh) { load_chunk(ch + 1, (ch + 1) & 1); CP_WAIT1(); }
        else              { CP_WAIT0(); }
        __syncthreads();
        const uint32_t stg  = sb + (ch & 1) * STG;
        const uint32_t sAhi = stg, sAlo = stg + 16384;
        const uint32_t sBhi = stg + 32768, sBlo = stg + 49152;
#pragma unroll
        for (int ks = 0; ks < 4; ks++) {
            const int kb = ks * 32;
            uint32_t ah[4][4], bh[2][4];
#pragma unroll
            for (int mt = 0; mt < 4; mt++)
                LDSM4(ah[mt], sAhi + off128(wm + mt * 16 + aRow, kb + aKb));
#pragma unroll
            for (int n2 = 0; n2 < 2; n2++)
                LDSM4(bh[n2], sBhi + off128(wn + n2 * 16 + bRow, kb + bKb));
#pragma unroll
            for (int mt = 0; mt < 4; mt++)
#pragma unroll
                for (int nt = 0; nt < 4; nt++)
                    MMA_BF16(acc[mt][nt], ah[mt], &bh[nt >> 1][(nt & 1) * 2]);
            uint32_t al[4][4];
#pragma unroll
            for (int mt = 0; mt < 4; mt++)
                LDSM4(al[mt], sAlo + off128(wm + mt * 16 + aRow, kb + aKb));
#pragma unroll
            for (int mt = 0; mt < 4; mt++)
#pragma unroll
                for (int nt = 0; nt < 4; nt++)
                    MMA_BF16(acc[mt][nt], al[mt], &bh[nt >> 1][(nt & 1) * 2]);
            uint32_t bl[2][4];
#pragma unroll
            for (int n2 = 0; n2 < 2; n2++)
                LDSM4(bl[n2], sBlo + off128(wn + n2 * 16 + bRow, kb + bKb));
#pragma unroll
            for (int mt = 0; mt < 4; mt++)
#pragma unroll
                for (int nt = 0; nt < 4; nt++)
                    MMA_BF16(acc[mt][nt], ah[mt], &bl[nt >> 1][(nt & 1) * 2]);
        }
        __syncthreads();
    }

    const int r0 = lane >> 2, c0 = (lane & 3) * 2;
#pragma unroll
    for (int mt = 0; mt < 4; mt++) {
        int m0 = bm + wm + mt * 16 + r0;
#pragma unroll
        for (int nt = 0; nt < 4; nt++) {
            int n = bn + wn + nt * 8 + c0;
            float b0 = bias[n], b1 = bias[n + 1];
            float v00 = acc[mt][nt][0] + b0, v01 = acc[mt][nt][1] + b1;
            float v10 = acc[mt][nt][2] + b0, v11 = acc[mt][nt][3] + b1;
            if (C) {
                *(float2*)&C[(size_t)m0 * N + n] = {v00, v01};
                *(float2*)&C[(size_t)(m0 + 8) * N + n] = {v10, v11};
            } else {
                bf16 h0, l0, h1, l1;
                split_bf(v00, h0, l0); split_bf(v01, h1, l1);
                *(bf162*)&Chi[(size_t)m0 * N + n] = __halves2bfloat162(h0, h1);
                *(bf162*)&Clo[(size_t)m0 * N + n] = __halves2bfloat162(l0, l1);
                split_bf(v10, h0, l0); split_bf(v11, h1, l1);
                *(bf162*)&Chi[(size_t)(m0 + 8) * N + n] = __halves2bfloat162(h0, h1);
                *(bf162*)&Clo[(size_t)(m0 + 8) * N + n] = __halves2bfloat162(l0, l1);
            }
        }
    }
}

// ---------------------------------------------------------------------------
// Fused flash-style attention, all-MMA, split-bf16.
// CTA = (b, h, 128 q rows). 32 kv tiles of 64. 8 warps = 2q x 4(kv|dk).
// Per tile: S=QK^T (3-pass MMA) -> online softmax (cross-warp via smem) ->
// p' to gmem + split-bf16 P to smem -> O += P@V (3-pass MMA, rescaled).
// Tail: ctx split-bf16 from fragments; in-place normalize sweep of p'.
// ---------------------------------------------------------------------------
#define QHI   0
#define QLO   16384
#define PHI   32768        // K hi/lo alias the P region (dead by P-write time)
#define KHI   32768
#define KLO   40960
#define PLO   49152
#define VTHI  65536
#define VTLO  73728
#define SNM   81920        // 32*128 floats
#define SRA   98304        // 4*128 floats
#define SRB   100352       // 4*128 floats
#define SML   102400       // 128 float2
#define ATTN_SMEM 103424

__global__ __launch_bounds__(256, 2) void attn_mma(
    const bf16* __restrict__ Qh, const bf16* __restrict__ Ql,
    const bf16* __restrict__ Kh, const bf16* __restrict__ Kl,
    const bf16* __restrict__ Vh, const bf16* __restrict__ Vl,
    float* __restrict__ attn, bf16* __restrict__ Ch, bf16* __restrict__ Cl)
{
    extern __shared__ char sm[];
    const uint32_t sb = smem_u32(sm);
    float* sNM  = (float*)(sm + SNM);
    float* sRA  = (float*)(sm + SRA);
    float* sRB  = (float*)(sm + SRB);
    float2* sML = (float2*)(sm + SML);

    const int b = blockIdx.z, h = blockIdx.y, q0 = blockIdx.x * 128;
    const int tid = threadIdx.x, lane = tid & 31, wid = tid >> 5;
    const int wq = wid >> 2, wk4 = wid & 3;      // wk4: kv-warp (QK) / dk-warp (PV)
    const int r0 = lane >> 2, c0 = (lane & 3) * 2;
    const int aRow = lane & 15,                       aKb = (lane >> 4) * 16;
    const int bRow = (lane & 7) + ((lane >> 4) << 3), bKb = ((lane >> 3) & 1) * 16;
    const float scale = 0.125f;

    const size_t rowQ0 = (size_t)b * SEQ + q0;
    const int hoff = h * DK;
    float* attnB = attn + ((size_t)(b * NHEADS + h)) * SEQ * SEQ;

    // Load Q tile (hi/lo) [128 q][64 dk]
    for (int s = 0; s < 4; s++) {
        int idx = tid + s * 256;                 // 1024 uint4 per buffer
        int r = idx >> 3, g = idx & 7;
        uint32_t so = off128(r, g * 16);
        *(uint4*)(sm + QHI + so) = *(const uint4*)&Qh[(rowQ0 + r) * DMODEL + hoff + g * 8];
        *(uint4*)(sm + QLO + so) = *(const uint4*)&Ql[(rowQ0 + r) * DMODEL + hoff + g * 8];
    }

    float m[8], l[8], acc_o[4][2][4];
#pragma unroll
    for (int i = 0; i < 8; i++) { m[i] = -1e30f; l[i] = 0.f; }
#pragma unroll
    for (int i = 0; i < 4; i++)
#pragma unroll
        for (int j = 0; j < 2; j++)
#pragma unroll
            for (int r = 0; r < 4; r++) acc_o[i][j][r] = 0.f;
    __syncthreads();

    for (int kt = 0; kt < 32; kt++) {
        // K tile [64 kv][64 dk]
        for (int s = 0; s < 2; s++) {
            int idx = tid + s * 256;             // 512 uint4 per buffer
            int r = idx >> 3, g = idx & 7;
            uint32_t so = off128(r, g * 16);
            size_t gr = ((size_t)b * SEQ + kt * 64 + r) * DMODEL + hoff + g * 8;
            *(uint4*)(sm + KHI + so) = *(const uint4*)&Kh[gr];
            *(uint4*)(sm + KLO + so) = *(const uint4*)&Kl[gr];
        }
        __syncthreads();

        // S = Q @ K^T (3 passes)
        float acc[4][2][4];
#pragma unroll
        for (int i = 0; i < 4; i++)
#pragma unroll
            for (int j = 0; j < 2; j++)
#pragma unroll
                for (int r = 0; r < 4; r++) acc[i][j][r] = 0.f;
#pragma unroll
        for (int ks = 0; ks < 4; ks++) {
            const int kb = ks * 32;
            uint32_t ah[4][4], bh[4], al[4][4], bl[4];
#pragma unroll
            for (int mt = 0; mt < 4; mt++)
                LDSM4(ah[mt], sb + QHI + off128(wq * 64 + mt * 16 + aRow, kb + aKb));
            LDSM4(bh, sb + KHI + off128(wk4 * 16 + bRow, kb + bKb));
#pragma unroll
            for (int mt = 0; mt < 4; mt++)
#pragma unroll
                for (int nt = 0; nt < 2; nt++)
                    MMA_BF16(acc[mt][nt], ah[mt], &bh[nt * 2]);
#pragma unroll
            for (int mt = 0; mt < 4; mt++)
                LDSM4(al[mt], sb + QLO + off128(wq * 64 + mt * 16 + aRow, kb + aKb));
#pragma unroll
            for (int mt = 0; mt < 4; mt++)
#pragma unroll
                for (int nt = 0; nt < 2; nt++)
                    MMA_BF16(acc[mt][nt], al[mt], &bh[nt * 2]);
            LDSM4(bl, sb + KLO + off128(wk4 * 16 + bRow, kb + bKb));
#pragma unroll
            for (int mt = 0; mt < 4; mt++)
#pragma unroll
                for (int nt = 0; nt < 2; nt++)
                    MMA_BF16(acc[mt][nt], ah[mt], &bl[nt * 2]);
        }

        // scale + warp-local row max -> sRA
#pragma unroll
        for (int mt = 0; mt < 4; mt++)
#pragma unroll
            for (int h2 = 0; h2 < 2; h2++) {
                float v = -1e30f;
#pragma unroll
                for (int nt = 0; nt < 2; nt++)
#pragma unroll
                    for (int j = 0; j < 2; j++) {
                        acc[mt][nt][h2 * 2 + j] *= scale;
                        v = fmaxf(v, acc[mt][nt][h2 * 2 + j]);
                    }
                v = fmaxf(v, __shfl_xor_sync(~0u, v, 1));
                v = fmaxf(v, __shfl_xor_sync(~0u, v, 2));
                if ((lane & 3) == 0)
                    sRA[wk4 * 128 + wq * 64 + mt * 16 + h2 * 8 + r0] = v;
            }
        __syncthreads();   // all QK MMA done; K dead; sRA complete

        // softmax: exp, p' out, P smem, partial sums, VT load
#pragma unroll
        for (int mt = 0; mt < 4; mt++)
#pragma unroll
            for (int h2 = 0; h2 < 2; h2++) {
                int s = mt * 2 + h2;
                int rowL = wq * 64 + mt * 16 + h2 * 8 + r0;
                float tmax = fmaxf(fmaxf(sRA[rowL], sRA[128 + rowL]),
                                   fmaxf(sRA[256 + rowL], sRA[384 + rowL]));
                float nm = fmaxf(m[s], tmax);
                float resc = __expf(m[s] - nm);
                float sum = 0.f;
#pragma unroll
                for (int nt = 0; nt < 2; nt++) {
                    float p0 = __expf(acc[mt][nt][h2 * 2 + 0] - nm);
                    float p1 = __expf(acc[mt][nt][h2 * 2 + 1] - nm);
                    sum += p0 + p1;
                    int col = wk4 * 16 + nt * 8 + c0;
                    *(float2*)&attnB[(size_t)(q0 + rowL) * SEQ + kt * 64 + col] = {p0, p1};
                    bf16 ph0, pl0, ph1, pl1;
                    split_bf(p0, ph0, pl0); split_bf(p1, ph1, pl1);
                    *(bf162*)(sm + PHI + off128(rowL, col * 2)) = __halves2bfloat162(ph0, ph1);
                    *(bf162*)(sm + PLO + off128(rowL, col * 2)) = __halves2bfloat162(pl0, pl1);
                }
                sum += __shfl_xor_sync(~0u, sum, 1);
                sum += __shfl_xor_sync(~0u, sum, 2);
                if ((lane & 3) == 0) sRB[wk4 * 128 + rowL] = sum;
                // rescale O accumulators
#pragma unroll
                for (int nt = 0; nt < 2; nt++)
#pragma unroll
                    for (int j = 0; j < 2; j++) acc_o[mt][nt][h2 * 2 + j] *= resc;
                l[s] *= resc;
                m[s] = nm;
                if (wk4 == 0 && (lane & 3) == 0) sNM[kt * 128 + rowL] = nm;
            }
        // V^T tiles [64 dk][64 kv]
        for (int i = tid; i < 64 * 32; i += 256) {
            int kv = i >> 5, dp = (i & 31) * 2;
            size_t gr = ((size_t)b * SEQ + kt * 64 + kv) * DMODEL + hoff + dp;
            bf162 vh = *(const bf162*)&Vh[gr];
            bf162 vl = *(const bf162*)&Vl[gr];
            *(bf16*)(sm + VTHI + off128(dp,     kv * 2)) = vh.x;
            *(bf16*)(sm + VTHI + off128(dp + 1, kv * 2)) = vh.y;
            *(bf16*)(sm + VTLO + off128(dp,     kv * 2)) = vl.x;
            *(bf16*)(sm + VTLO + off128(dp + 1, kv * 2)) = vl.y;
        }
        __syncthreads();   // P, VT, sRB complete

        // finish l with cross-warp sums
#pragma unroll
        for (int mt = 0; mt < 4; mt++)
#pragma unroll
            for (int h2 = 0; h2 < 2; h2++) {
                int rowL = wq * 64 + mt * 16 + h2 * 8 + r0;
                l[mt * 2 + h2] += sRB[rowL] + sRB[128 + rowL] + sRB[256 + rowL] + sRB[384 + rowL];
            }

        // O += P @ V (3 passes). wk4 = dk-warp here.
#pragma unroll
        for (int ks = 0; ks < 4; ks++) {
            const int kb = ks * 32;
            uint32_t ap[4][4], bp[4], al2[4][4], bl2[4];
#pragma unroll
            for (int mt = 0; mt < 4; mt++)
                LDSM4(ap[mt], sb + PHI + off128(wq * 64 + mt * 16 + aRow, kb + aKb));
            LDSM4(bp, sb + VTHI + off128(wk4 * 16 + bRow, kb + bKb));
#pragma unroll
            for (int mt = 0; mt < 4; mt++)
#pragma unroll
                for (int nt = 0; nt < 2; nt++)
                    MMA_BF16(acc_o[mt][nt], ap[mt], &bp[nt * 2]);
#pragma unroll
            for (int mt = 0; mt < 4; mt++)
                LDSM4(al2[mt], sb + PLO + off128(wq * 64 + mt * 16 + aRow, kb + aKb));
#pragma unroll
            for (int mt = 0; mt < 4; mt++)
#pragma unroll
                for (int nt = 0; nt < 2; nt++)
                    MMA_BF16(acc_o[mt][nt], al2[mt], &bp[nt * 2]);
            LDSM4(bl2, sb + VTLO + off128(wk4 * 16 + bRow, kb + bKb));
#pragma unroll
            for (int mt = 0; mt < 4; mt++)
#pragma unroll
                for (int nt = 0; nt < 2; nt++)
                    MMA_BF16(acc_o[mt][nt], ap[mt], &bl2[nt * 2]);
        }
        __syncthreads();   // PV done before next tile overwrites P/K region
    }

    // ctx = O / l, split bf16
#pragma unroll
    for (int mt = 0; mt < 4; mt++)
#pragma unroll
        for (int h2 = 0; h2 < 2; h2++) {
            int s = mt * 2 + h2;
            float il = 1.f / l[s];
            int rowL = wq * 64 + mt * 16 + h2 * 8 + r0;
#pragma unroll
            for (int nt = 0; nt < 2; nt++) {
                float v0 = acc_o[mt][nt][h2 * 2 + 0] * il;
                float v1 = acc_o[mt][nt][h2 * 2 + 1] * il;
                bf16 h0, l0, h1, l1;
                split_bf(v0, h0, l0); split_bf(v1, h1, l1);
                size_t go = (rowQ0 + rowL) * DMODEL + hoff + wk4 * 16 + nt * 8 + c0;
                *(bf162*)&Ch[go] = __halves2bfloat162(h0, h1);
                *(bf162*)&Cl[go] = __halves2bfloat162(l0, l1);
            }
            if (wk4 == 0 && (lane & 3) == 0) sML[rowL] = {m[s], 1.f / l[s]};
        }
    __syncthreads();
    // fac table: sNM <- exp(nm - m_final) / l
    for (int i = tid; i < 32 * 128; i += 256) {
        int row = i & 127;
        float2 ml = sML[row];
        sNM[i] = __expf(sNM[i] - ml.x) * ml.y;
    }
    __syncthreads();
    // normalize sweep: P = p' * fac
    for (int i = tid; i < 128 * 512; i += 256) {
        int row = i >> 9, f4 = i & 511;
        float fac = sNM[((f4 >> 4) << 7) + row];
        float4* gp = (float4*)&attnB[(size_t)(q0 + row) * SEQ + f4 * 4];
        float4 v = *gp;
        v.x *= fac; v.y *= fac; v.z *= fac; v.w *= fac;
        *gp = v;
    }
}

// ---------------------------------------------------------------------------
extern "C" void kernel_launch(void* const* d_in, const int* in_sizes, int n_in,
                              void* d_out, int out_size)
{
    const float* q  = (const float*)d_in[0];
    const float* k  = (const float*)d_in[1];
    const float* v  = (const float*)d_in[2];
    const float* wq = (const float*)d_in[3];
    const float* bq = (const float*)d_in[4];
    const float* wk = (const float*)d_in[5];
    const float* bk = (const float*)d_in[6];
    const float* wv = (const float*)d_in[7];
    const float* bv = (const float*)d_in[8];
    const float* wo = (const float*)d_in[9];
    const float* bo = (const float*)d_in[10];

    float* out  = (float*)d_out;
    float* attn = out + (size_t)MROWS * DMODEL;

    bf16 *Aqh, *Aql, *Akh, *Akl, *Avh, *Avl;
    bf16 *Wqh, *Wql, *Wkh, *Wkl, *Wvh, *Wvl, *Woh, *Wol;
    bf16 *Qh, *Ql, *Kh, *Kl, *Vh, *Vl, *Ch, *Cl;
    cudaGetSymbolAddress((void**)&Aqh, g_Aqh); cudaGetSymbolAddress((void**)&Aql, g_Aql);
    cudaGetSymbolAddress((void**)&Akh, g_Akh); cudaGetSymbolAddress((void**)&Akl, g_Akl);
    cudaGetSymbolAddress((void**)&Avh, g_Avh); cudaGetSymbolAddress((void**)&Avl, g_Avl);
    cudaGetSymbolAddress((void**)&Wqh, g_Wqh); cudaGetSymbolAddress((void**)&Wql, g_Wql);
    cudaGetSymbolAddress((void**)&Wkh, g_Wkh); cudaGetSymbolAddress((void**)&Wkl, g_Wkl);
    cudaGetSymbolAddress((void**)&Wvh, g_Wvh); cudaGetSymbolAddress((void**)&Wvl, g_Wvl);
    cudaGetSymbolAddress((void**)&Woh, g_Woh); cudaGetSymbolAddress((void**)&Wol, g_Wol);
    cudaGetSymbolAddress((void**)&Qh, g_Qh);   cudaGetSymbolAddress((void**)&Ql, g_Ql);
    cudaGetSymbolAddress((void**)&Kh, g_Kh);   cudaGetSymbolAddress((void**)&Kl, g_Kl);
    cudaGetSymbolAddress((void**)&Vh, g_Vh);   cudaGetSymbolAddress((void**)&Vl, g_Vl);
    cudaGetSymbolAddress((void**)&Ch, g_Ch);   cudaGetSymbolAddress((void**)&Cl, g_Cl);

    static int attr_set = 0;
    if (!attr_set) {
        cudaFuncSetAttribute(gemm_mma, cudaFuncAttributeMaxDynamicSharedMemorySize, GEMM_SMEM);
        cudaFuncSetAttribute(attn_mma, cudaFuncAttributeMaxDynamicSharedMemorySize, ATTN_SMEM);
        attr_set = 1;
    }

    dim3 ggrid(DMODEL / 128, MROWS / 128); // (8, 32)

    cvt7<<<dim3(MROWS * DMODEL / 1024, 7), 256>>>(
        q, k, v, wq, wk, wv, wo,
        Aqh, Akh, Avh, Wqh, Wkh, Wvh, Woh,
        Aql, Akl, Avl, Wql, Wkl, Wvl, Wol);                               // 0

    gemm_mma<<<ggrid, 256, GEMM_SMEM>>>(Aqh, Aql, Wqh, Wql, bq,
        nullptr, Qh, Ql, MROWS, DMODEL, DMODEL);                          // 1
    gemm_mma<<<ggrid, 256, GEMM_SMEM>>>(Akh, Akl, Wkh, Wkl, bk,
        nullptr, Kh, Kl, MROWS, DMODEL, DMODEL);                          // 2
    gemm_mma<<<ggrid, 256, GEMM_SMEM>>>(Avh, Avl, Wvh, Wvl, bv,
        nullptr, Vh, Vl, MROWS, DMODEL, DMODEL);                          // 3

    attn_mma<<<dim3(SEQ / 128, NHEADS, BATCH), 256, ATTN_SMEM>>>(
        Qh, Ql, Kh, Kl, Vh, Vl, attn, Ch, Cl);                            // 4

    gemm_mma<<<ggrid, 256, GEMM_SMEM>>>(Ch, Cl, Woh, Wol, bo,
        out, nullptr, nullptr, MROWS, DMODEL, DMODEL);                    // 5
}

// round 14
// speedup vs baseline: 1.9541x; 1.1353x over previous
#include <cuda_runtime.h>
#include <cuda_bf16.h>
#include <stdint.h>

#define BATCH   2
#define SEQ     2048
#define DMODEL  1024
#define NHEADS  16
#define DK      64
#define MROWS   (BATCH*SEQ)      // 4096
typedef __nv_bfloat16  bf16;
typedef __nv_bfloat162 bf162;

// ---- scratch (__device__ globals: allocation-free rule) ----
__device__ bf16 g_Aqh[MROWS*DMODEL], g_Aql[MROWS*DMODEL];
__device__ bf16 g_Akh[MROWS*DMODEL], g_Akl[MROWS*DMODEL];
__device__ bf16 g_Avh[MROWS*DMODEL], g_Avl[MROWS*DMODEL];
__device__ bf16 g_Wqh[DMODEL*DMODEL], g_Wql[DMODEL*DMODEL];
__device__ bf16 g_Wkh[DMODEL*DMODEL], g_Wkl[DMODEL*DMODEL];
__device__ bf16 g_Wvh[DMODEL*DMODEL], g_Wvl[DMODEL*DMODEL];
__device__ bf16 g_Woh[DMODEL*DMODEL], g_Wol[DMODEL*DMODEL];
__device__ bf16 g_Qh[MROWS*DMODEL], g_Ql[MROWS*DMODEL];
__device__ bf16 g_Kh[MROWS*DMODEL], g_Kl[MROWS*DMODEL];
__device__ bf16 g_Vh[MROWS*DMODEL], g_Vl[MROWS*DMODEL];
__device__ bf16 g_Ch[MROWS*DMODEL], g_Cl[MROWS*DMODEL];

__device__ __forceinline__ uint32_t smem_u32(const void* p) {
    uint32_t a;
    asm("{ .reg .u64 t; cvta.to.shared.u64 t, %1; cvt.u32.u64 %0, t; }" : "=r"(a) : "l"(p));
    return a;
}

#define LDSM4(r, addr) asm volatile( \
    "ldmatrix.sync.aligned.m8n8.x4.shared.b16 {%0,%1,%2,%3}, [%4];" \
    : "=r"((r)[0]), "=r"((r)[1]), "=r"((r)[2]), "=r"((r)[3]) : "r"(addr))

#define LDSM4_T(r, addr) asm volatile( \
    "ldmatrix.sync.aligned.m8n8.x4.trans.shared.b16 {%0,%1,%2,%3}, [%4];" \
    : "=r"((r)[0]), "=r"((r)[1]), "=r"((r)[2]), "=r"((r)[3]) : "r"(addr))

#define MMA_BF16(d, a, b) asm volatile( \
    "mma.sync.aligned.m16n8k16.row.col.f32.bf16.bf16.f32 " \
    "{%0,%1,%2,%3}, {%4,%5,%6,%7}, {%8,%9}, {%0,%1,%2,%3};" \
    : "+f"((d)[0]), "+f"((d)[1]), "+f"((d)[2]), "+f"((d)[3]) \
    : "r"((a)[0]), "r"((a)[1]), "r"((a)[2]), "r"((a)[3]), "r"((b)[0]), "r"((b)[1]))

__device__ __forceinline__ void cp16(uint32_t saddr, const void* g) {
    asm volatile("cp.async.cg.shared.global [%0], [%1], 16;" :: "r"(saddr), "l"(g));
}
#define CP_COMMIT() asm volatile("cp.async.commit_group;" ::: "memory")
#define CP_WAIT1()  asm volatile("cp.async.wait_group 1;" ::: "memory")
#define CP_WAIT0()  asm volatile("cp.async.wait_group 0;" ::: "memory")

// 128B-row swizzled tile: byte offset of (row, kb bytes within 128B row)
__device__ __forceinline__ uint32_t off128(int row, int kb) {
    return row * 128 + ((((kb >> 4) ^ (row & 7)) & 7) << 4) + (kb & 15);
}

__device__ __forceinline__ void split_bf(float v, bf16& h, bf16& l) {
    h = __float2bfloat16(v);
    l = __float2bfloat16(v - __bfloat162float(h));
}

// ---------------------------------------------------------------------------
// cvt7: split 7 fp32 tensors (q,k,v 4M; wq,wk,wv,wo 1M) into bf16 hi/lo.
// ---------------------------------------------------------------------------
__global__ __launch_bounds__(256) void cvt7(
    const float* x0, const float* x1, const float* x2, const float* x3,
    const float* x4, const float* x5, const float* x6,
    bf16* h0, bf16* h1, bf16* h2, bf16* h3, bf16* h4, bf16* h5, bf16* h6,
    bf16* l0, bf16* l1, bf16* l2, bf16* l3, bf16* l4, bf16* l5, bf16* l6)
{
    const float* xs[7] = {x0, x1, x2, x3, x4, x5, x6};
    bf16* hs[7] = {h0, h1, h2, h3, h4, h5, h6};
    bf16* ls[7] = {l0, l1, l2, l3, l4, l5, l6};
    int t = blockIdx.y;
    int n = (t < 3) ? MROWS * DMODEL : DMODEL * DMODEL;
    int i = (blockIdx.x * 256 + threadIdx.x) * 4;
    if (i >= n) return;
    float4 v = *(const float4*)(xs[t] + i);
    bf16 a, b, c, d, e, f, g, h;
    split_bf(v.x, a, e); split_bf(v.y, b, f);
    split_bf(v.z, c, g); split_bf(v.w, d, h);
    *(bf162*)(hs[t] + i)     = __halves2bfloat162(a, b);
    *(bf162*)(hs[t] + i + 2) = __halves2bfloat162(c, d);
    *(bf162*)(ls[t] + i)     = __halves2bfloat162(e, f);
    *(bf162*)(ls[t] + i + 2) = __halves2bfloat162(g, h);
}

// ---------------------------------------------------------------------------
// mma.sync GEMM: 3-pass split-bf16, 2-stage cp.async. Output either fp32
// (C != null) or split bf16 (Chi/Clo).
// ---------------------------------------------------------------------------
#define STG       65536
#define GEMM_SMEM (2*STG)

__global__ __launch_bounds__(256) void gemm_mma(
    const bf16* __restrict__ Ahi, const bf16* __restrict__ Alo,
    const bf16* __restrict__ Whi, const bf16* __restrict__ Wlo,
    const float* __restrict__ bias, float* __restrict__ C,
    bf16* __restrict__ Chi, bf16* __restrict__ Clo,
    int M, int N, int K)
{
    extern __shared__ char sm[];
    const uint32_t sb = smem_u32(sm);
    const int tid = threadIdx.x, lane = tid & 31, wid = tid >> 5;
    const int wm = (wid >> 2) * 64, wn = (wid & 3) * 32;
    const int bm = blockIdx.y * 128, bn = blockIdx.x * 128;
    const int aRow = lane & 15,                       aKb = (lane >> 4) * 16;
    const int bRow = (lane & 7) + ((lane >> 4) << 3), bKb = ((lane >> 3) & 1) * 16;

    float acc[4][4][4];
#pragma unroll
    for (int i = 0; i < 4; i++)
#pragma unroll
        for (int j = 0; j < 4; j++)
#pragma unroll
            for (int r = 0; r < 4; r++) acc[i][j][r] = 0.f;

    const int nCh = K / 64;
    auto load_chunk = [&](int ch, int st) {
        const int k0 = ch * 64;
        const uint32_t stg = sb + st * STG;
#pragma unroll
        for (int s = 0; s < 4; s++) {
            int idx = tid + s * 256;
            int r = idx >> 3, g = idx & 7;
            uint32_t so = r * 128 + ((g ^ (r & 7)) << 4);
            const size_t ga = (size_t)(bm + r) * K + k0 + g * 8;
            const size_t gb = (size_t)(bn + r) * K + k0 + g * 8;
            cp16(stg + so,         Ahi + ga);
            cp16(stg + 16384 + so, Alo + ga);
            cp16(stg + 32768 + so, Whi + gb);
            cp16(stg + 49152 + so, Wlo + gb);
        }
        CP_COMMIT();
    };

    load_chunk(0, 0);
    for (int ch = 0; ch < nCh; ch++) {
        if (ch + 1 < nCh) { load_chunk(ch + 1, (ch + 1) & 1); CP_WAIT1(); }
        else              { CP_WAIT0(); }
        __syncthreads();
        const uint32_t stg  = sb + (ch & 1) * STG;
        const uint32_t sAhi = stg, sAlo = stg + 16384;
        const uint32_t sBhi = stg + 32768, sBlo = stg + 49152;
#pragma unroll
        for (int ks = 0; ks < 4; ks++) {
            const int kb = ks * 32;
            uint32_t ah[4][4], bh[2][4];
#pragma unroll
            for (int mt = 0; mt < 4; mt++)
                LDSM4(ah[mt], sAhi + off128(wm + mt * 16 + aRow, kb + aKb));
#pragma unroll
            for (int n2 = 0; n2 < 2; n2++)
                LDSM4(bh[n2], sBhi + off128(wn + n2 * 16 + bRow, kb + bKb));
#pragma unroll
            for (int mt = 0; mt < 4; mt++)
#pragma unroll
                for (int nt = 0; nt < 4; nt++)
                    MMA_BF16(acc[mt][nt], ah[mt], &bh[nt >> 1][(nt & 1) * 2]);
            uint32_t al[4][4];
#pragma unroll
            for (int mt = 0; mt < 4; mt++)
                LDSM4(al[mt], sAlo + off128(wm + mt * 16 + aRow, kb + aKb));
#pragma unroll
            for (int mt = 0; mt < 4; mt++)
#pragma unroll
                for (int nt = 0; nt < 4; nt++)
                    MMA_BF16(acc[mt][nt], al[mt], &bh[nt >> 1][(nt & 1) * 2]);
            uint32_t bl[2][4];
#pragma unroll
            for (int n2 = 0; n2 < 2; n2++)
                LDSM4(bl[n2], sBlo + off128(wn + n2 * 16 + bRow, kb + bKb));
#pragma unroll
            for (int mt = 0; mt < 4; mt++)
#pragma unroll
                for (int nt = 0; nt < 4; nt++)
                    MMA_BF16(acc[mt][nt], ah[mt], &bl[nt >> 1][(nt & 1) * 2]);
        }
        __syncthreads();
    }

    const int r0 = lane >> 2, c0 = (lane & 3) * 2;
#pragma unroll
    for (int mt = 0; mt < 4; mt++) {
        int m0 = bm + wm + mt * 16 + r0;
#pragma unroll
        for (int nt = 0; nt < 4; nt++) {
            int n = bn + wn + nt * 8 + c0;
            float b0 = bias[n], b1 = bias[n + 1];
            float v00 = acc[mt][nt][0] + b0, v01 = acc[mt][nt][1] + b1;
            float v10 = acc[mt][nt][2] + b0, v11 = acc[mt][nt][3] + b1;
            if (C) {
                *(float2*)&C[(size_t)m0 * N + n] = {v00, v01};
                *(float2*)&C[(size_t)(m0 + 8) * N + n] = {v10, v11};
            } else {
                bf16 h0, l0, h1, l1;
                split_bf(v00, h0, l0); split_bf(v01, h1, l1);
                *(bf162*)&Chi[(size_t)m0 * N + n] = __halves2bfloat162(h0, h1);
                *(bf162*)&Clo[(size_t)m0 * N + n] = __halves2bfloat162(l0, l1);
                split_bf(v10, h0, l0); split_bf(v11, h1, l1);
                *(bf162*)&Chi[(size_t)(m0 + 8) * N + n] = __halves2bfloat162(h0, h1);
                *(bf162*)&Clo[(size_t)(m0 + 8) * N + n] = __halves2bfloat162(l0, l1);
            }
        }
    }
}

// ---------------------------------------------------------------------------
// Fused flash-style attention, all-MMA, split-bf16.
// V kept in natural [kv][dk] layout; P@V B-operand via ldmatrix .trans
// (no scalar transpose). K/V tile loads via cp.async at tile top.
// K hi/lo region is reused for P hi/lo after QK completes.
// ---------------------------------------------------------------------------
#define QHI   0
#define QLO   16384
#define PHI   32768        // K hi/lo alias the P region (dead by P-write time)
#define KHI   32768
#define KLO   40960
#define PLO   49152
#define VHI   65536        // V natural [64 kv][64 dk] hi
#define VLO   73728        // V natural lo
#define SNM   81920        // 32*128 floats
#define SRA   98304        // 4*128 floats
#define SRB   100352       // 4*128 floats
#define SML   102400       // 128 float2
#define ATTN_SMEM 103424

__global__ __launch_bounds__(256, 2) void attn_mma(
    const bf16* __restrict__ Qh, const bf16* __restrict__ Ql,
    const bf16* __restrict__ Kh, const bf16* __restrict__ Kl,
    const bf16* __restrict__ Vh, const bf16* __restrict__ Vl,
    float* __restrict__ attn, bf16* __restrict__ Ch, bf16* __restrict__ Cl)
{
    extern __shared__ char sm[];
    const uint32_t sb = smem_u32(sm);
    float* sNM  = (float*)(sm + SNM);
    float* sRA  = (float*)(sm + SRA);
    float* sRB  = (float*)(sm + SRB);
    float2* sML = (float2*)(sm + SML);

    const int b = blockIdx.z, h = blockIdx.y, q0 = blockIdx.x * 128;
    const int tid = threadIdx.x, lane = tid & 31, wid = tid >> 5;
    const int wq = wid >> 2, wk4 = wid & 3;      // wk4: kv-warp (QK) / dk-warp (PV)
    const int r0 = lane >> 2, c0 = (lane & 3) * 2;
    const int aRow = lane & 15,                       aKb = (lane >> 4) * 16;
    const int bRow = (lane & 7) + ((lane >> 4) << 3), bKb = ((lane >> 3) & 1) * 16;
    // trans-ldmatrix lane geometry for V^T fragments
    const int vRow8 = ((lane >> 3) & 1) * 8 + (lane & 7);      // kv within 16-chunk
    const int vColB = (wk4 * 16 + ((lane >> 4) << 3)) * 2;     // dk byte offset
    const float scale = 0.125f;

    const size_t rowQ0 = (size_t)b * SEQ + q0;
    const int hoff = h * DK;
    float* attnB = attn + ((size_t)(b * NHEADS + h)) * SEQ * SEQ;

    // Load Q tile (hi/lo) [128 q][64 dk]
    for (int s = 0; s < 4; s++) {
        int idx = tid + s * 256;                 // 1024 uint4 per buffer
        int r = idx >> 3, g = idx & 7;
        uint32_t so = off128(r, g * 16);
        cp16(sb + QHI + so, &Qh[(rowQ0 + r) * DMODEL + hoff + g * 8]);
        cp16(sb + QLO + so, &Ql[(rowQ0 + r) * DMODEL + hoff + g * 8]);
    }
    CP_COMMIT();

    float m[8], l[8], acc_o[4][2][4];
#pragma unroll
    for (int i = 0; i < 8; i++) { m[i] = -1e30f; l[i] = 0.f; }
#pragma unroll
    for (int i = 0; i < 4; i++)
#pragma unroll
        for (int j = 0; j < 2; j++)
#pragma unroll
            for (int r = 0; r < 4; r++) acc_o[i][j][r] = 0.f;

    for (int kt = 0; kt < 32; kt++) {
        // K tile [64 kv][64 dk] + V tile [64 kv][64 dk], both natural layout
        for (int s = 0; s < 2; s++) {
            int idx = tid + s * 256;             // 512 uint4 per buffer
            int r = idx >> 3, g = idx & 7;
            uint32_t so = off128(r, g * 16);
            size_t gr = ((size_t)b * SEQ + kt * 64 + r) * DMODEL + hoff + g * 8;
            cp16(sb + KHI + so, &Kh[gr]);
            cp16(sb + KLO + so, &Kl[gr]);
            cp16(sb + VHI + so, &Vh[gr]);
            cp16(sb + VLO + so, &Vl[gr]);
        }
        CP_COMMIT();
        CP_WAIT0();
        __syncthreads();

        // S = Q @ K^T (3 passes)
        float acc[4][2][4];
#pragma unroll
        for (int i = 0; i < 4; i++)
#pragma unroll
            for (int j = 0; j < 2; j++)
#pragma unroll
                for (int r = 0; r < 4; r++) acc[i][j][r] = 0.f;
#pragma unroll
        for (int ks = 0; ks < 4; ks++) {
            const int kb = ks * 32;
            uint32_t ah[4][4], bh[4], al[4][4], bl[4];
#pragma unroll
            for (int mt = 0; mt < 4; mt++)
                LDSM4(ah[mt], sb + QHI + off128(wq * 64 + mt * 16 + aRow, kb + aKb));
            LDSM4(bh, sb + KHI + off128(wk4 * 16 + bRow, kb + bKb));
#pragma unroll
            for (int mt = 0; mt < 4; mt++)
#pragma unroll
                for (int nt = 0; nt < 2; nt++)
                    MMA_BF16(acc[mt][nt], ah[mt], &bh[nt * 2]);
#pragma unroll
            for (int mt = 0; mt < 4; mt++)
                LDSM4(al[mt], sb + QLO + off128(wq * 64 + mt * 16 + aRow, kb + aKb));
#pragma unroll
            for (int mt = 0; mt < 4; mt++)
#pragma unroll
                for (int nt = 0; nt < 2; nt++)
                    MMA_BF16(acc[mt][nt], al[mt], &bh[nt * 2]);
            LDSM4(bl, sb + KLO + off128(wk4 * 16 + bRow, kb + bKb));
#pragma unroll
            for (int mt = 0; mt < 4; mt++)
#pragma unroll
                for (int nt = 0; nt < 2; nt++)
                    MMA_BF16(acc[mt][nt], ah[mt], &bl[nt * 2]);
        }

        // scale + warp-local row max -> sRA
#pragma unroll
        for (int mt = 0; mt < 4; mt++)
#pragma unroll
            for (int h2 = 0; h2 < 2; h2++) {
                float v = -1e30f;
#pragma unroll
                for (int nt = 0; nt < 2; nt++)
#pragma unroll
                    for (int j = 0; j < 2; j++) {
                        acc[mt][nt][h2 * 2 + j] *= scale;
                        v = fmaxf(v, acc[mt][nt][h2 * 2 + j]);
                    }
                v = fmaxf(v, __shfl_xor_sync(~0u, v, 1));
                v = fmaxf(v, __shfl_xor_sync(~0u, v, 2));
                if ((lane & 3) == 0)
                    sRA[wk4 * 128 + wq * 64 + mt * 16 + h2 * 8 + r0] = v;
            }
        __syncthreads();   // all QK MMA done; K dead; sRA complete

        // softmax: exp, p' out, split-bf16 P into K region, partial sums
#pragma unroll
        for (int mt = 0; mt < 4; mt++)
#pragma unroll
            for (int h2 = 0; h2 < 2; h2++) {
                int s = mt * 2 + h2;
                int rowL = wq * 64 + mt * 16 + h2 * 8 + r0;
                float tmax = fmaxf(fmaxf(sRA[rowL], sRA[128 + rowL]),
                                   fmaxf(sRA[256 + rowL], sRA[384 + rowL]));
                float nm = fmaxf(m[s], tmax);
                float resc = __expf(m[s] - nm);
                float sum = 0.f;
#pragma unroll
                for (int nt = 0; nt < 2; nt++) {
                    float p0 = __expf(acc[mt][nt][h2 * 2 + 0] - nm);
                    float p1 = __expf(acc[mt][nt][h2 * 2 + 1] - nm);
                    sum += p0 + p1;
                    int col = wk4 * 16 + nt * 8 + c0;
                    *(float2*)&attnB[(size_t)(q0 + rowL) * SEQ + kt * 64 + col] = {p0, p1};
                    bf16 ph0, pl0, ph1, pl1;
                    split_bf(p0, ph0, pl0); split_bf(p1, ph1, pl1);
                    *(bf162*)(sm + PHI + off128(rowL, col * 2)) = __halves2bfloat162(ph0, ph1);
                    *(bf162*)(sm + PLO + off128(rowL, col * 2)) = __halves2bfloat162(pl0, pl1);
                }
                sum += __shfl_xor_sync(~0u, sum, 1);
                sum += __shfl_xor_sync(~0u, sum, 2);
                if ((lane & 3) == 0) sRB[wk4 * 128 + rowL] = sum;
                // rescale O accumulators
#pragma unroll
                for (int nt = 0; nt < 2; nt++)
#pragma unroll
                    for (int j = 0; j < 2; j++) acc_o[mt][nt][h2 * 2 + j] *= resc;
                l[s] *= resc;
                m[s] = nm;
                if (wk4 == 0 && (lane & 3) == 0) sNM[kt * 128 + rowL] = nm;
            }
        __syncthreads();   // P, sRB complete

        // finish l with cross-warp sums
#pragma unroll
        for (int mt = 0; mt < 4; mt++)
#pragma unroll
            for (int h2 = 0; h2 < 2; h2++) {
                int rowL = wq * 64 + mt * 16 + h2 * 8 + r0;
                l[mt * 2 + h2] += sRB[rowL] + sRB[128 + rowL] + sRB[256 + rowL] + sRB[384 + rowL];
            }

        // O += P @ V (3 passes). B-operand = V^T via ldmatrix.trans.
#pragma unroll
        for (int ks = 0; ks < 4; ks++) {
            const int kb = ks * 32;
            uint32_t ap[4][4], bp[4], al2[4][4], bl2[4];
#pragma unroll
            for (int mt = 0; mt < 4; mt++)
                LDSM4(ap[mt], sb + PHI + off128(wq * 64 + mt * 16 + aRow, kb + aKb));
            LDSM4_T(bp, sb + VHI + off128(ks * 16 + vRow8, vColB));
#pragma unroll
            for (int mt = 0; mt < 4; mt++)
#pragma unroll
                for (int nt = 0; nt < 2; nt++)
                    MMA_BF16(acc_o[mt][nt], ap[mt], &bp[nt * 2]);
#pragma unroll
            for (int mt = 0; mt < 4; mt++)
                LDSM4(al2[mt], sb + PLO + off128(wq * 64 + mt * 16 + aRow, kb + aKb));
#pragma unroll
            for (int mt = 0; mt < 4; mt++)
#pragma unroll
                for (int nt = 0; nt < 2; nt++)
                    MMA_BF16(acc_o[mt][nt], al2[mt], &bp[nt * 2]);
            LDSM4_T(bl2, sb + VLO + off128(ks * 16 + vRow8, vColB));
#pragma unroll
            for (int mt = 0; mt < 4; mt++)
#pragma unroll
                for (int nt = 0; nt < 2; nt++)
                    MMA_BF16(acc_o[mt][nt], ap[mt], &bl2[nt * 2]);
        }
        __syncthreads();   // PV done before next tile overwrites K/P and V
    }

    // ctx = O / l, split bf16
#pragma unroll
    for (int mt = 0; mt < 4; mt++)
#pragma unroll
        for (int h2 = 0; h2 < 2; h2++) {
            int s = mt * 2 + h2;
            float il = 1.f / l[s];
            int rowL = wq * 64 + mt * 16 + h2 * 8 + r0;
#pragma unroll
            for (int nt = 0; nt < 2; nt++) {
                float v0 = acc_o[mt][nt][h2 * 2 + 0] * il;
                float v1 = acc_o[mt][nt][h2 * 2 + 1] * il;
                bf16 h0, l0, h1, l1;
                split_bf(v0, h0, l0); split_bf(v1, h1, l1);
                size_t go = (rowQ0 + rowL) * DMODEL + hoff + wk4 * 16 + nt * 8 + c0;
                *(bf162*)&Ch[go] = __halves2bfloat162(h0, h1);
                *(bf162*)&Cl[go] = __halves2bfloat162(l0, l1);
            }
            if (wk4 == 0 && (lane & 3) == 0) sML[rowL] = {m[s], 1.f / l[s]};
        }
    __syncthreads();
    // fac table: sNM <- exp(nm - m_final) / l
    for (int i = tid; i < 32 * 128; i += 256) {
        int row = i & 127;
        float2 ml = sML[row];
        sNM[i] = __expf(sNM[i] - ml.x) * ml.y;
    }
    __syncthreads();
    // normalize sweep: P = p' * fac
    for (int i = tid; i < 128 * 512; i += 256) {
        int row = i >> 9, f4 = i & 511;
        float fac = sNM[((f4 >> 4) << 7) + row];
        float4* gp = (float4*)&attnB[(size_t)(q0 + row) * SEQ + f4 * 4];
        float4 v = *gp;
        v.x *= fac; v.y *= fac; v.z *= fac; v.w *= fac;
        *gp = v;
    }
}

// ---------------------------------------------------------------------------
extern "C" void kernel_launch(void* const* d_in, const int* in_sizes, int n_in,
                              void* d_out, int out_size)
{
    const float* q  = (const float*)d_in[0];
    const float* k  = (const float*)d_in[1];
    const float* v  = (const float*)d_in[2];
    const float* wq = (const float*)d_in[3];
    const float* bq = (const float*)d_in[4];
    const float* wk = (const float*)d_in[5];
    const float* bk = (const float*)d_in[6];
    const float* wv = (const float*)d_in[7];
    const float* bv = (const float*)d_in[8];
    const float* wo = (const float*)d_in[9];
    const float* bo = (const float*)d_in[10];

    float* out  = (float*)d_out;
    float* attn = out + (size_t)MROWS * DMODEL;

    bf16 *Aqh, *Aql, *Akh, *Akl, *Avh, *Avl;
    bf16 *Wqh, *Wql, *Wkh, *Wkl, *Wvh, *Wvl, *Woh, *Wol;
    bf16 *Qh, *Ql, *Kh, *Kl, *Vh, *Vl, *Ch, *Cl;
    cudaGetSymbolAddress((void**)&Aqh, g_Aqh); cudaGetSymbolAddress((void**)&Aql, g_Aql);
    cudaGetSymbolAddress((void**)&Akh, g_Akh); cudaGetSymbolAddress((void**)&Akl, g_Akl);
    cudaGetSymbolAddress((void**)&Avh, g_Avh); cudaGetSymbolAddress((void**)&Avl, g_Avl);
    cudaGetSymbolAddress((void**)&Wqh, g_Wqh); cudaGetSymbolAddress((void**)&Wql, g_Wql);
    cudaGetSymbolAddress((void**)&Wkh, g_Wkh); cudaGetSymbolAddress((void**)&Wkl, g_Wkl);
    cudaGetSymbolAddress((void**)&Wvh, g_Wvh); cudaGetSymbolAddress((void**)&Wvl, g_Wvl);
    cudaGetSymbolAddress((void**)&Woh, g_Woh); cudaGetSymbolAddress((void**)&Wol, g_Wol);
    cudaGetSymbolAddress((void**)&Qh, g_Qh);   cudaGetSymbolAddress((void**)&Ql, g_Ql);
    cudaGetSymbolAddress((void**)&Kh, g_Kh);   cudaGetSymbolAddress((void**)&Kl, g_Kl);
    cudaGetSymbolAddress((void**)&Vh, g_Vh);   cudaGetSymbolAddress((void**)&Vl, g_Vl);
    cudaGetSymbolAddress((void**)&Ch, g_Ch);   cudaGetSymbolAddress((void**)&Cl, g_Cl);

    static int attr_set = 0;
    if (!attr_set) {
        cudaFuncSetAttribute(gemm_mma, cudaFuncAttributeMaxDynamicSharedMemorySize, GEMM_SMEM);
        cudaFuncSetAttribute(attn_mma, cudaFuncAttributeMaxDynamicSharedMemorySize, ATTN_SMEM);
        attr_set = 1;
    }

    dim3 ggrid(DMODEL / 128, MROWS / 128); // (8, 32)

    cvt7<<<dim3(MROWS * DMODEL / 1024, 7), 256>>>(
        q, k, v, wq, wk, wv, wo,
        Aqh, Akh, Avh, Wqh, Wkh, Wvh, Woh,
        Aql, Akl, Avl, Wql, Wkl, Wvl, Wol);                               // 0

    gemm_mma<<<ggrid, 256, GEMM_SMEM>>>(Aqh, Aql, Wqh, Wql, bq,
        nullptr, Qh, Ql, MROWS, DMODEL, DMODEL);                          // 1
    gemm_mma<<<ggrid, 256, GEMM_SMEM>>>(Akh, Akl, Wkh, Wkl, bk,
        nullptr, Kh, Kl, MROWS, DMODEL, DMODEL);                          // 2
    gemm_mma<<<ggrid, 256, GEMM_SMEM>>>(Avh, Avl, Wvh, Wvl, bv,
        nullptr, Vh, Vl, MROWS, DMODEL, DMODEL);                          // 3

    attn_mma<<<dim3(SEQ / 128, NHEADS, BATCH), 256, ATTN_SMEM>>>(
        Qh, Ql, Kh, Kl, Vh, Vl, attn, Ch, Cl);                            // 4

    gemm_mma<<<ggrid, 256, GEMM_SMEM>>>(Ch, Cl, Woh, Wol, bo,
        out, nullptr, nullptr, MROWS, DMODEL, DMODEL);                    // 5
}